// round 2
// baseline (speedup 1.0000x reference)
#include <cuda_runtime.h>
#include <math.h>

// Problem constants
#define NB   4
#define CI   64        // I
#define CC   256       // C
#define GG   8         // groups
#define CG   32        // C/G
#define KK   9
#define HH   48
#define WW   48
#define HW   (HH*WW)   // 2304
#define HD   40
#define WD   40
#define DD   (HD*WD)   // 1600
#define C2   (2*CC)    // 512
#define CPG  64        // 2C/G: conv input channels per group
#define STRIDE_GATE (NB*CC*HW)

// Scratch (static device globals; allocation-free rule)
__device__ float g_xh[NB*C2*HW];       // interleaved [N][G][2][Cg][H][W]
__device__ float g_q [NB*CC*HW];
__device__ float g_k [NB*CC*DD];
__device__ float g_v [NB*CC*DD];
__device__ float g_a [NB*CC*HW];
__device__ float g_gate[4*STRIDE_GATE];

// ---------------------------------------------------------------------------
// Kernel 1: x = Wx*inp + Wxg*h  (1x1 convs), write interleaved xh (x and h)
// grid (72, 4), block 256 (thread = out channel)
// ---------------------------------------------------------------------------
__global__ __launch_bounds__(256) void proj_kernel(
    const float* __restrict__ inp, const float* __restrict__ h,
    const float* __restrict__ Wx,  const float* __restrict__ Wxg)
{
    __shared__ float s_in[CI][32];
    __shared__ float s_h [CC][32];
    const int n  = blockIdx.y;
    const int p0 = blockIdx.x * 32;
    const int t  = threadIdx.x;

    for (int i = t; i < CI*32; i += 256) {
        int ch = i >> 5, p = i & 31;
        s_in[ch][p] = inp[(n*CI + ch)*HW + p0 + p];
    }
    for (int i = t; i < CC*32; i += 256) {
        int ch = i >> 5, p = i & 31;
        s_h[ch][p] = h[(n*CC + ch)*HW + p0 + p];
    }
    __syncthreads();

    const int c = t, g = c >> 5, cg = c & 31;
    float acc[32];
    #pragma unroll
    for (int p = 0; p < 32; p++) acc[p] = 0.f;

    const float4* wx4 = reinterpret_cast<const float4*>(Wx + c*CI);
    for (int ci4 = 0; ci4 < CI/4; ci4++) {
        float4 w = wx4[ci4];
        int cb = ci4 * 4;
        #pragma unroll
        for (int p = 0; p < 32; p++)
            acc[p] += w.x*s_in[cb][p] + w.y*s_in[cb+1][p]
                    + w.z*s_in[cb+2][p] + w.w*s_in[cb+3][p];
    }
    const float4* wg4 = reinterpret_cast<const float4*>(Wxg + c*CC);
    for (int ci4 = 0; ci4 < CC/4; ci4++) {
        float4 w = wg4[ci4];
        int cb = ci4 * 4;
        #pragma unroll
        for (int p = 0; p < 32; p++)
            acc[p] += w.x*s_h[cb][p] + w.y*s_h[cb+1][p]
                    + w.z*s_h[cb+2][p] + w.w*s_h[cb+3][p];
    }
    float* xh_x = g_xh + ((size_t)(n*C2 + g*CPG + cg))*HW + p0;
    float* xh_h = g_xh + ((size_t)(n*C2 + g*CPG + CG + cg))*HW + p0;
    #pragma unroll
    for (int p = 0; p < 32; p++) {
        xh_x[p] = acc[p];
        xh_h[p] = s_h[c][p];
    }
}

// ---------------------------------------------------------------------------
// Direct tiled grouped 9x9 conv body.
// Block: 256 threads = 16 columns x 16 rows, each thread covers 3 y-positions
// (y, y+16, y+32) for 8 output channels -> 24 accumulators.
// Input tile in smem: 2 channels x 56 rows x 24 cols (row stride 48 ->
// conflict-free for the 2-rows-per-warp access pattern).
// ---------------------------------------------------------------------------
__device__ __forceinline__ void conv9_body(
    const float* __restrict__ in_ptr,   // group input base [64][HW]
    const float* __restrict__ wt,       // weight base for oc0: [8][64][81]
    float* __restrict__ outp,           // output base for oc0: [8][OUTH*OUTW]
    int tx0, int OUTH, int OUTW, int PAD)
{
    __shared__ float s_in[2][56][48];
    __shared__ float s_w [8][2][81];
    const int t  = threadIdx.x;
    const int x  = t & 15;
    const int ty = t >> 4;

    float acc[3][8];
    #pragma unroll
    for (int j = 0; j < 3; j++)
        #pragma unroll
        for (int oc = 0; oc < 8; oc++) acc[j][oc] = 0.f;

    for (int ci0 = 0; ci0 < CPG; ci0 += 2) {
        __syncthreads();
        // input tile (zero-padded / bounds-guarded)
        for (int i = t; i < 2*56*24; i += 256) {
            int ci  = i / (56*24);
            int rem = i - ci*(56*24);
            int r   = rem / 24;
            int cc  = rem - r*24;
            int gy  = r - PAD;
            int gx  = tx0 + cc - PAD;
            float val = 0.f;
            if (gy >= 0 && gy < HH && gx >= 0 && gx < WW)
                val = in_ptr[(ci0 + ci)*HW + gy*WW + gx];
            s_in[ci][r][cc] = val;
        }
        // weights
        for (int i = t; i < 8*2*81; i += 256) {
            int oc  = i / 162;
            int rem = i - oc*162;
            int ci  = rem / 81;
            int kk  = rem - ci*81;
            s_w[oc][ci][kk] = wt[oc*(CPG*81) + (ci0 + ci)*81 + kk];
        }
        __syncthreads();

        #pragma unroll
        for (int ci = 0; ci < 2; ci++) {
            for (int ky = 0; ky < 9; ky++) {
                #pragma unroll
                for (int kx = 0; kx < 9; kx++) {
                    float v0 = s_in[ci][ty      + ky][x + kx];
                    float v1 = s_in[ci][ty + 16 + ky][x + kx];
                    float v2 = s_in[ci][ty + 32 + ky][x + kx];
                    #pragma unroll
                    for (int oc = 0; oc < 8; oc++) {
                        float w = s_w[oc][ci][ky*9 + kx];
                        acc[0][oc] = fmaf(w, v0, acc[0][oc]);
                        acc[1][oc] = fmaf(w, v1, acc[1][oc]);
                        acc[2][oc] = fmaf(w, v2, acc[2][oc]);
                    }
                }
            }
        }
    }

    const int ox = tx0 + x;
    if (ox < OUTW) {
        #pragma unroll
        for (int j = 0; j < 3; j++) {
            int oy = ty + 16*j;
            if (oy < OUTH) {
                #pragma unroll
                for (int oc = 0; oc < 8; oc++)
                    outp[oc*OUTH*OUTW + oy*OUTW + ox] = acc[j][oc];
            }
        }
    }
}

// q conv: SAME, grid (3, 4, 32)
__global__ __launch_bounds__(256) void conv_q_kernel(const float* __restrict__ Wq)
{
    int n = blockIdx.z >> 3, g = blockIdx.z & 7;
    int oc0 = blockIdx.y * 8;
    conv9_body(g_xh + ((size_t)(n*C2 + g*CPG))*HW,
               Wq   + ((size_t)(g*CG + oc0))*(CPG*81),
               g_q  + ((size_t)(n*CC + g*CG + oc0))*HW,
               blockIdx.x*16, HH, WW, 4);
}

// k & v convs: VALID, grid (3, 8, 32); blockIdx.y<4 -> k, else v
__global__ __launch_bounds__(256) void conv_kv_kernel(
    const float* __restrict__ Wk, const float* __restrict__ Wv)
{
    int n = blockIdx.z >> 3, g = blockIdx.z & 7;
    int sel = blockIdx.y >> 2;
    int oc0 = (blockIdx.y & 3) * 8;
    const float* W = sel ? Wv : Wk;
    float* out     = sel ? g_v : g_k;
    conv9_body(g_xh + ((size_t)(n*C2 + g*CPG))*HW,
               W    + ((size_t)(g*CG + oc0))*(CPG*81),
               out  + ((size_t)(n*CC + g*CG + oc0))*DD,
               blockIdx.x*16, HD, WD, 0);
}

// 4 gate convs (pre-activation): SAME, grid (3, 16, 32); blockIdx.y>>2 = gate
__global__ __launch_bounds__(256) void conv_gate_kernel(
    const float* __restrict__ W0, const float* __restrict__ W1,
    const float* __restrict__ W2, const float* __restrict__ W3)
{
    int n = blockIdx.z >> 3, g = blockIdx.z & 7;
    int gate = blockIdx.y >> 2;
    int oc0  = (blockIdx.y & 3) * 8;
    const float* W = (gate == 0) ? W0 : (gate == 1) ? W1 : (gate == 2) ? W2 : W3;
    conv9_body(g_xh   + ((size_t)(n*C2 + g*CPG))*HW,
               W      + ((size_t)(g*CG + oc0))*(CPG*81),
               g_gate + (size_t)gate*STRIDE_GATE + ((size_t)(n*CC + g*CG + oc0))*HW,
               blockIdx.x*16, HH, WW, 4);
}

// ---------------------------------------------------------------------------
// Kernel 3: attention. grid (288, 32), block 256 = 8 warps = 8 query rows.
// Each lane owns 50 of the 1600 key positions (d = lane + 32*j), scores in
// registers; k/v staged through a 32x320 smem chunk (5 chunks).
// ---------------------------------------------------------------------------
__global__ __launch_bounds__(256) void attn_kernel(const float* __restrict__ tau)
{
    __shared__ float s_kv[CG][320];
    __shared__ float s_q [8][CG];
    const int ngi = blockIdx.y;
    const int n = ngi >> 3, g = ngi & 7;
    const int r0 = blockIdx.x * 8;
    const int t = threadIdx.x, warp = t >> 5, lane = t & 31;

    for (int i = t; i < 8*CG; i += 256) {
        int r = i >> 5, c = i & 31;
        s_q[r][c] = g_q[((size_t)(n*CC + g*CG + c))*HW + r0 + r];
    }

    float sc[50];
    #pragma unroll
    for (int ch = 0; ch < 5; ch++) {
        __syncthreads();
        for (int i = t; i < CG*320; i += 256) {
            int c = i / 320, dd = i - c*320;
            s_kv[c][dd] = g_k[((size_t)(n*CC + g*CG + c))*DD + ch*320 + dd];
        }
        __syncthreads();
        float accd[10];
        #pragma unroll
        for (int j = 0; j < 10; j++) accd[j] = 0.f;
        for (int c = 0; c < CG; c++) {
            float qv = s_q[warp][c];
            #pragma unroll
            for (int j = 0; j < 10; j++)
                accd[j] = fmaf(qv, s_kv[c][lane + 32*j], accd[j]);
        }
        #pragma unroll
        for (int j = 0; j < 10; j++) sc[ch*10 + j] = accd[j];
    }

    const float tg = tau[g];
    float m = -1e30f;
    #pragma unroll
    for (int j = 0; j < 50; j++) { sc[j] *= tg; m = fmaxf(m, sc[j]); }
    #pragma unroll
    for (int o = 16; o > 0; o >>= 1)
        m = fmaxf(m, __shfl_xor_sync(0xffffffffu, m, o));
    float s = 0.f;
    #pragma unroll
    for (int j = 0; j < 50; j++) { sc[j] = __expf(sc[j] - m); s += sc[j]; }
    #pragma unroll
    for (int o = 16; o > 0; o >>= 1)
        s += __shfl_xor_sync(0xffffffffu, s, o);
    const float inv = 1.f / s;
    #pragma unroll
    for (int j = 0; j < 50; j++) sc[j] *= inv;

    float acco[CG];
    #pragma unroll
    for (int c = 0; c < CG; c++) acco[c] = 0.f;
    #pragma unroll
    for (int ch = 0; ch < 5; ch++) {
        __syncthreads();
        for (int i = t; i < CG*320; i += 256) {
            int c = i / 320, dd = i - c*320;
            s_kv[c][dd] = g_v[((size_t)(n*CC + g*CG + c))*DD + ch*320 + dd];
        }
        __syncthreads();
        #pragma unroll
        for (int j = 0; j < 10; j++) {
            float pv = sc[ch*10 + j];
            #pragma unroll
            for (int c = 0; c < CG; c++)
                acco[c] = fmaf(pv, s_kv[c][lane + 32*j], acco[c]);
        }
    }

    float myout = 0.f;
    #pragma unroll
    for (int c = 0; c < CG; c++) {
        float v = acco[c];
        #pragma unroll
        for (int o = 16; o > 0; o >>= 1)
            v += __shfl_xor_sync(0xffffffffu, v, o);
        if (lane == c) myout = v;
    }
    g_a[((size_t)(n*CC + g*CG + lane))*HW + r0 + warp] = myout;
}

// ---------------------------------------------------------------------------
// Kernel 4: grouped 1x1 Wa*a + gate pre-activations + bias -> LSTM update.
// grid (288, 4), block 256 (thread = out channel), 8 spatial positions/block.
// ---------------------------------------------------------------------------
__device__ __forceinline__ float sigmoidf_(float x) { return 1.f / (1.f + __expf(-x)); }

__global__ __launch_bounds__(256) void lstm_kernel(
    const float* __restrict__ Wa0, const float* __restrict__ Wa1,
    const float* __restrict__ Wa2, const float* __restrict__ Wa3,
    const float* __restrict__ b0,  const float* __restrict__ b1,
    const float* __restrict__ b2,  const float* __restrict__ b3,
    const float* __restrict__ c_prev, float* __restrict__ out)
{
    __shared__ float s_a[CC][8];
    const int n  = blockIdx.y;
    const int p0 = blockIdx.x * 8;
    const int t  = threadIdx.x;

    for (int i = t; i < CC*8; i += 256) {
        int ch = i >> 3, p = i & 7;
        s_a[ch][p] = g_a[((size_t)(n*CC + ch))*HW + p0 + p];
    }
    __syncthreads();

    const int c = t, g = c >> 5;
    float a0[8], a1[8], a2[8], a3[8];
    #pragma unroll
    for (int p = 0; p < 8; p++) { a0[p] = a1[p] = a2[p] = a3[p] = 0.f; }

    const float* wa0 = Wa0 + c*CG;
    const float* wa1 = Wa1 + c*CG;
    const float* wa2 = Wa2 + c*CG;
    const float* wa3 = Wa3 + c*CG;
    for (int cg = 0; cg < CG; cg++) {
        float w0 = wa0[cg], w1 = wa1[cg], w2 = wa2[cg], w3 = wa3[cg];
        const float* ar = s_a[g*CG + cg];
        #pragma unroll
        for (int p = 0; p < 8; p++) {
            float av = ar[p];
            a0[p] = fmaf(w0, av, a0[p]);
            a1[p] = fmaf(w1, av, a1[p]);
            a2[p] = fmaf(w2, av, a2[p]);
            a3[p] = fmaf(w3, av, a3[p]);
        }
    }

    const float bi = b0[c], bf = b1[c], bg = b2[c], bo = b3[c];
    const int idx0 = (n*CC + c)*HW + p0;
    #pragma unroll
    for (int p = 0; p < 8; p++) {
        int idx = idx0 + p;
        float gi = sigmoidf_(a0[p] + g_gate[                 idx] + bi);
        float gf = sigmoidf_(a1[p] + g_gate[  STRIDE_GATE  + idx] + bf);
        float gg = tanhf    (a2[p] + g_gate[2*STRIDE_GATE  + idx] + bg);
        float go = sigmoidf_(a3[p] + g_gate[3*STRIDE_GATE  + idx] + bo);
        float cn = gf * c_prev[idx] + gi * gg;
        out[idx] = go * tanhf(cn);
    }
}

// ---------------------------------------------------------------------------
extern "C" void kernel_launch(void* const* d_in, const int* in_sizes, int n_in,
                              void* d_out, int out_size)
{
    const float* inp    = (const float*)d_in[0];
    const float* h_prev = (const float*)d_in[1];
    const float* c_prev = (const float*)d_in[2];
    const float* Wx     = (const float*)d_in[3];
    const float* Wxg    = (const float*)d_in[4];
    const float* tau    = (const float*)d_in[5];
    const float* Wq     = (const float*)d_in[6];
    const float* Wk     = (const float*)d_in[7];
    const float* Wv     = (const float*)d_in[8];
    const float* Wa_i   = (const float*)d_in[9];
    const float* Wxh_i  = (const float*)d_in[10];
    const float* b_i    = (const float*)d_in[11];
    const float* Wa_f   = (const float*)d_in[12];
    const float* Wxh_f  = (const float*)d_in[13];
    const float* b_f    = (const float*)d_in[14];
    const float* Wa_g   = (const float*)d_in[15];
    const float* Wxh_g  = (const float*)d_in[16];
    const float* b_g    = (const float*)d_in[17];
    const float* Wa_o   = (const float*)d_in[18];
    const float* Wxh_o  = (const float*)d_in[19];
    const float* b_o    = (const float*)d_in[20];
    float* out = (float*)d_out;

    proj_kernel     <<<dim3(HW/32, NB), 256>>>(inp, h_prev, Wx, Wxg);
    conv_q_kernel   <<<dim3(3, 4, NB*GG), 256>>>(Wq);
    conv_kv_kernel  <<<dim3(3, 8, NB*GG), 256>>>(Wk, Wv);
    conv_gate_kernel<<<dim3(3, 16, NB*GG), 256>>>(Wxh_i, Wxh_f, Wxh_g, Wxh_o);
    attn_kernel     <<<dim3(HW/8, NB*GG), 256>>>(tau);
    lstm_kernel     <<<dim3(HW/8, NB), 256>>>(Wa_i, Wa_f, Wa_g, Wa_o,
                                              b_i, b_f, b_g, b_o, c_prev, out);
}

// round 3
// speedup vs baseline: 1.2988x; 1.2988x over previous
#include <cuda_runtime.h>
#include <math.h>

// Problem constants
#define NB   4
#define CI   64        // I
#define CC   256       // C
#define GG   8         // groups
#define CG   32        // C/G
#define KK   9
#define HH   48
#define WW   48
#define HW   (HH*WW)   // 2304
#define HD   40
#define WD   40
#define DD   (HD*WD)   // 1600
#define C2   (2*CC)    // 512
#define CPG  64        // 2C/G: conv input channels per group
#define STRIDE_GATE (NB*CC*HW)

typedef unsigned long long u64;

// Scratch (static device globals; allocation-free rule)
__device__ float g_xh[NB*C2*HW];       // interleaved [N][G][2][Cg][H][W]
__device__ float g_q [NB*CC*HW];
__device__ float g_k [NB*CC*DD];
__device__ float g_v [NB*CC*DD];
__device__ float g_a [NB*CC*HW];
__device__ float g_gate[4*STRIDE_GATE];

// ---------------------------------------------------------------------------
// Packed fp32x2 helpers (Blackwell FFMA2: 2x fp32 peak, ptxas won't auto-fuse)
// ---------------------------------------------------------------------------
__device__ __forceinline__ void fma2(u64& d, const u64 a, const u64 b) {
    asm("fma.rn.f32x2 %0, %1, %2, %0;" : "+l"(d) : "l"(a), "l"(b));
}
__device__ __forceinline__ u64 dup2(float v) {
    u64 r;
    asm("mov.b64 %0, {%1, %1};" : "=l"(r) : "f"(v));
    return r;
}
__device__ __forceinline__ float lo2(u64 v) { float a, b; asm("mov.b64 {%0,%1}, %2;" : "=f"(a), "=f"(b) : "l"(v)); return a; }
__device__ __forceinline__ float hi2(u64 v) { float a, b; asm("mov.b64 {%0,%1}, %2;" : "=f"(a), "=f"(b) : "l"(v)); return b; }

// ---------------------------------------------------------------------------
// Kernel 1: x = Wx*inp + Wxg*h  (1x1 convs), write interleaved xh (x and h)
// grid (72, 4), block 256 (thread = out channel)
// ---------------------------------------------------------------------------
__global__ __launch_bounds__(256) void proj_kernel(
    const float* __restrict__ inp, const float* __restrict__ h,
    const float* __restrict__ Wx,  const float* __restrict__ Wxg)
{
    __shared__ float s_in[CI][32];
    __shared__ float s_h [CC][32];
    const int n  = blockIdx.y;
    const int p0 = blockIdx.x * 32;
    const int t  = threadIdx.x;

    for (int i = t; i < CI*32; i += 256) {
        int ch = i >> 5, p = i & 31;
        s_in[ch][p] = inp[(n*CI + ch)*HW + p0 + p];
    }
    for (int i = t; i < CC*32; i += 256) {
        int ch = i >> 5, p = i & 31;
        s_h[ch][p] = h[(n*CC + ch)*HW + p0 + p];
    }
    __syncthreads();

    const int c = t, g = c >> 5, cg = c & 31;
    float acc[32];
    #pragma unroll
    for (int p = 0; p < 32; p++) acc[p] = 0.f;

    const float4* wx4 = reinterpret_cast<const float4*>(Wx + c*CI);
    for (int ci4 = 0; ci4 < CI/4; ci4++) {
        float4 w = wx4[ci4];
        int cb = ci4 * 4;
        #pragma unroll
        for (int p = 0; p < 32; p++)
            acc[p] += w.x*s_in[cb][p] + w.y*s_in[cb+1][p]
                    + w.z*s_in[cb+2][p] + w.w*s_in[cb+3][p];
    }
    const float4* wg4 = reinterpret_cast<const float4*>(Wxg + c*CC);
    for (int ci4 = 0; ci4 < CC/4; ci4++) {
        float4 w = wg4[ci4];
        int cb = ci4 * 4;
        #pragma unroll
        for (int p = 0; p < 32; p++)
            acc[p] += w.x*s_h[cb][p] + w.y*s_h[cb+1][p]
                    + w.z*s_h[cb+2][p] + w.w*s_h[cb+3][p];
    }
    float* xh_x = g_xh + ((size_t)(n*C2 + g*CPG + cg))*HW + p0;
    float* xh_h = g_xh + ((size_t)(n*C2 + g*CPG + CG + cg))*HW + p0;
    #pragma unroll
    for (int p = 0; p < 32; p++) {
        xh_x[p] = acc[p];
        xh_h[p] = s_h[c][p];
    }
}

// ---------------------------------------------------------------------------
// Direct tiled grouped 9x9 conv body, packed-fp32x2 version.
// Block: 128 threads = 16 columns x 8 row-phases. Each thread computes NY
// y-positions (y = ty + 8*yy) for 8 output channels, held as 4 float2 pairs.
// Per (ci,ky,kx) step: NY input LDS.32 + 4 weight LDS.64 (broadcast)
// + 4*NY FFMA2 (8*NY fp32 FMA) -> FMA-bound at the packed fp32 rate.
// Input tile smem row stride 48 (== 16 mod 32): the 2-rows-per-warp access
// pattern is bank-conflict-free. Weight smem [ci][kk][oc] so oc pairs are
// contiguous 8B-aligned for LDS.64 broadcast.
// ---------------------------------------------------------------------------
template<int NY, int PAD, int OUTH, int OUTW>
__device__ __forceinline__ void conv9_body2(
    const float* __restrict__ in_ptr,   // group input base [64][HW]
    const float* __restrict__ wt,       // weight base for oc0: [8][64][81]
    float* __restrict__ outp,           // output base for oc0: [8][OUTH*OUTW]
    int tx0)
{
    __shared__ float s_in[2][56][48];
    __shared__ float s_w [2][81][8];
    const int t  = threadIdx.x;       // 128 threads
    const int x  = t & 15;
    const int ty = t >> 4;            // 0..7

    constexpr int ROWS = OUTH + 8;    // 56 (SAME) or 48 (VALID)

    u64 acc[NY][4];
    #pragma unroll
    for (int yy = 0; yy < NY; yy++)
        #pragma unroll
        for (int p = 0; p < 4; p++) acc[yy][p] = 0ull;

    for (int ci0 = 0; ci0 < CPG; ci0 += 2) {
        __syncthreads();
        // input tile (zero-padded / bounds-guarded): 2 x ROWS x 24 cols
        for (int i = t; i < 2*ROWS*24; i += 128) {
            int ci  = i / (ROWS*24);
            int rem = i - ci*(ROWS*24);
            int r   = rem / 24;
            int cc  = rem - r*24;
            int gy  = r - PAD;
            int gx  = tx0 + cc - PAD;
            float val = 0.f;
            if (gy >= 0 && gy < HH && gx >= 0 && gx < WW)
                val = in_ptr[(ci0 + ci)*HW + gy*WW + gx];
            s_in[ci][r][cc] = val;
        }
        // weights transposed to [ci][kk][oc]
        for (int i = t; i < 2*81*8; i += 128) {
            int ci  = i / (81*8);
            int rem = i - ci*(81*8);
            int kk  = rem >> 3;
            int oc  = rem & 7;
            s_w[ci][kk][oc] = wt[oc*(CPG*81) + (ci0 + ci)*81 + kk];
        }
        __syncthreads();

        #pragma unroll
        for (int ci = 0; ci < 2; ci++) {
            for (int ky = 0; ky < 9; ky++) {
                #pragma unroll
                for (int kx = 0; kx < 9; kx++) {
                    const int kk = ky*9 + kx;
                    u64 w0 = *reinterpret_cast<const u64*>(&s_w[ci][kk][0]);
                    u64 w1 = *reinterpret_cast<const u64*>(&s_w[ci][kk][2]);
                    u64 w2 = *reinterpret_cast<const u64*>(&s_w[ci][kk][4]);
                    u64 w3 = *reinterpret_cast<const u64*>(&s_w[ci][kk][6]);
                    #pragma unroll
                    for (int yy = 0; yy < NY; yy++) {
                        u64 vv = dup2(s_in[ci][ty + 8*yy + ky][x + kx]);
                        fma2(acc[yy][0], vv, w0);
                        fma2(acc[yy][1], vv, w1);
                        fma2(acc[yy][2], vv, w2);
                        fma2(acc[yy][3], vv, w3);
                    }
                }
            }
        }
    }

    const int ox = tx0 + x;
    if (ox < OUTW) {
        #pragma unroll
        for (int yy = 0; yy < NY; yy++) {
            int oy = ty + 8*yy;
            if (oy < OUTH) {
                #pragma unroll
                for (int p = 0; p < 4; p++) {
                    outp[(2*p  )*OUTH*OUTW + oy*OUTW + ox] = lo2(acc[yy][p]);
                    outp[(2*p+1)*OUTH*OUTW + oy*OUTW + ox] = hi2(acc[yy][p]);
                }
            }
        }
    }
}

// SAME-pad convs: q + 4 gates merged. grid (3, 20, 32), block 128.
// blockIdx.y: conv = y/4 (0=q, 1..4=gates i,f,g,o), ocblk = y%4.
__global__ __launch_bounds__(128) void conv_same_kernel(
    const float* __restrict__ Wq,
    const float* __restrict__ W0, const float* __restrict__ W1,
    const float* __restrict__ W2, const float* __restrict__ W3)
{
    int n = blockIdx.z >> 3, g = blockIdx.z & 7;
    int conv = blockIdx.y >> 2;
    int oc0  = (blockIdx.y & 3) * 8;
    const float* W = (conv == 0) ? Wq : (conv == 1) ? W0 :
                     (conv == 2) ? W1 : (conv == 3) ? W2 : W3;
    float* out = (conv == 0) ? g_q + ((size_t)(n*CC + g*CG + oc0))*HW
               : g_gate + (size_t)(conv-1)*STRIDE_GATE
                        + ((size_t)(n*CC + g*CG + oc0))*HW;
    conv9_body2<6, 4, HH, WW>(
        g_xh + ((size_t)(n*C2 + g*CPG))*HW,
        W    + ((size_t)(g*CG + oc0))*(CPG*81),
        out, blockIdx.x*16);
}

// k & v convs: VALID, grid (3, 8, 32); blockIdx.y<4 -> k, else v
__global__ __launch_bounds__(128) void conv_kv_kernel(
    const float* __restrict__ Wk, const float* __restrict__ Wv)
{
    int n = blockIdx.z >> 3, g = blockIdx.z & 7;
    int sel = blockIdx.y >> 2;
    int oc0 = (blockIdx.y & 3) * 8;
    const float* W = sel ? Wv : Wk;
    float* out     = sel ? g_v : g_k;
    conv9_body2<5, 0, HD, WD>(
        g_xh + ((size_t)(n*C2 + g*CPG))*HW,
        W    + ((size_t)(g*CG + oc0))*(CPG*81),
        out  + ((size_t)(n*CC + g*CG + oc0))*DD,
        blockIdx.x*16);
}

// ---------------------------------------------------------------------------
// Kernel 3: attention. grid (288, 32), block 256 = 8 warps = 8 query rows.
// Each lane owns 50 of the 1600 key positions (d = lane + 32*j), scores in
// registers; k/v staged through a 32x320 smem chunk (5 chunks).
// ---------------------------------------------------------------------------
__global__ __launch_bounds__(256) void attn_kernel(const float* __restrict__ tau)
{
    __shared__ float s_kv[CG][320];
    __shared__ float s_q [8][CG];
    const int ngi = blockIdx.y;
    const int n = ngi >> 3, g = ngi & 7;
    const int r0 = blockIdx.x * 8;
    const int t = threadIdx.x, warp = t >> 5, lane = t & 31;

    for (int i = t; i < 8*CG; i += 256) {
        int r = i >> 5, c = i & 31;
        s_q[r][c] = g_q[((size_t)(n*CC + g*CG + c))*HW + r0 + r];
    }

    float sc[50];
    #pragma unroll
    for (int ch = 0; ch < 5; ch++) {
        __syncthreads();
        for (int i = t; i < CG*320; i += 256) {
            int c = i / 320, dd = i - c*320;
            s_kv[c][dd] = g_k[((size_t)(n*CC + g*CG + c))*DD + ch*320 + dd];
        }
        __syncthreads();
        float accd[10];
        #pragma unroll
        for (int j = 0; j < 10; j++) accd[j] = 0.f;
        for (int c = 0; c < CG; c++) {
            float qv = s_q[warp][c];
            #pragma unroll
            for (int j = 0; j < 10; j++)
                accd[j] = fmaf(qv, s_kv[c][lane + 32*j], accd[j]);
        }
        #pragma unroll
        for (int j = 0; j < 10; j++) sc[ch*10 + j] = accd[j];
    }

    const float tg = tau[g];
    float m = -1e30f;
    #pragma unroll
    for (int j = 0; j < 50; j++) { sc[j] *= tg; m = fmaxf(m, sc[j]); }
    #pragma unroll
    for (int o = 16; o > 0; o >>= 1)
        m = fmaxf(m, __shfl_xor_sync(0xffffffffu, m, o));
    float s = 0.f;
    #pragma unroll
    for (int j = 0; j < 50; j++) { sc[j] = __expf(sc[j] - m); s += sc[j]; }
    #pragma unroll
    for (int o = 16; o > 0; o >>= 1)
        s += __shfl_xor_sync(0xffffffffu, s, o);
    const float inv = 1.f / s;
    #pragma unroll
    for (int j = 0; j < 50; j++) sc[j] *= inv;

    float acco[CG];
    #pragma unroll
    for (int c = 0; c < CG; c++) acco[c] = 0.f;
    #pragma unroll
    for (int ch = 0; ch < 5; ch++) {
        __syncthreads();
        for (int i = t; i < CG*320; i += 256) {
            int c = i / 320, dd = i - c*320;
            s_kv[c][dd] = g_v[((size_t)(n*CC + g*CG + c))*DD + ch*320 + dd];
        }
        __syncthreads();
        #pragma unroll
        for (int j = 0; j < 10; j++) {
            float pv = sc[ch*10 + j];
            #pragma unroll
            for (int c = 0; c < CG; c++)
                acco[c] = fmaf(pv, s_kv[c][lane + 32*j], acco[c]);
        }
    }

    float myout = 0.f;
    #pragma unroll
    for (int c = 0; c < CG; c++) {
        float v = acco[c];
        #pragma unroll
        for (int o = 16; o > 0; o >>= 1)
            v += __shfl_xor_sync(0xffffffffu, v, o);
        if (lane == c) myout = v;
    }
    g_a[((size_t)(n*CC + g*CG + lane))*HW + r0 + warp] = myout;
}

// ---------------------------------------------------------------------------
// Kernel 4: grouped 1x1 Wa*a + gate pre-activations + bias -> LSTM update.
// grid (288, 4), block 256 (thread = out channel), 8 spatial positions/block.
// ---------------------------------------------------------------------------
__device__ __forceinline__ float sigmoidf_(float x) { return 1.f / (1.f + __expf(-x)); }

__global__ __launch_bounds__(256) void lstm_kernel(
    const float* __restrict__ Wa0, const float* __restrict__ Wa1,
    const float* __restrict__ Wa2, const float* __restrict__ Wa3,
    const float* __restrict__ b0,  const float* __restrict__ b1,
    const float* __restrict__ b2,  const float* __restrict__ b3,
    const float* __restrict__ c_prev, float* __restrict__ out)
{
    __shared__ float s_a[CC][8];
    const int n  = blockIdx.y;
    const int p0 = blockIdx.x * 8;
    const int t  = threadIdx.x;

    for (int i = t; i < CC*8; i += 256) {
        int ch = i >> 3, p = i & 7;
        s_a[ch][p] = g_a[((size_t)(n*CC + ch))*HW + p0 + p];
    }
    __syncthreads();

    const int c = t, g = c >> 5;
    float a0[8], a1[8], a2[8], a3[8];
    #pragma unroll
    for (int p = 0; p < 8; p++) { a0[p] = a1[p] = a2[p] = a3[p] = 0.f; }

    const float* wa0 = Wa0 + c*CG;
    const float* wa1 = Wa1 + c*CG;
    const float* wa2 = Wa2 + c*CG;
    const float* wa3 = Wa3 + c*CG;
    for (int cg = 0; cg < CG; cg++) {
        float w0 = wa0[cg], w1 = wa1[cg], w2 = wa2[cg], w3 = wa3[cg];
        const float* ar = s_a[g*CG + cg];
        #pragma unroll
        for (int p = 0; p < 8; p++) {
            float av = ar[p];
            a0[p] = fmaf(w0, av, a0[p]);
            a1[p] = fmaf(w1, av, a1[p]);
            a2[p] = fmaf(w2, av, a2[p]);
            a3[p] = fmaf(w3, av, a3[p]);
        }
    }

    const float bi = b0[c], bf = b1[c], bg = b2[c], bo = b3[c];
    const int idx0 = (n*CC + c)*HW + p0;
    #pragma unroll
    for (int p = 0; p < 8; p++) {
        int idx = idx0 + p;
        float gi = sigmoidf_(a0[p] + g_gate[                 idx] + bi);
        float gf = sigmoidf_(a1[p] + g_gate[  STRIDE_GATE  + idx] + bf);
        float gg = tanhf    (a2[p] + g_gate[2*STRIDE_GATE  + idx] + bg);
        float go = sigmoidf_(a3[p] + g_gate[3*STRIDE_GATE  + idx] + bo);
        float cn = gf * c_prev[idx] + gi * gg;
        out[idx] = go * tanhf(cn);
    }
}

// ---------------------------------------------------------------------------
extern "C" void kernel_launch(void* const* d_in, const int* in_sizes, int n_in,
                              void* d_out, int out_size)
{
    const float* inp    = (const float*)d_in[0];
    const float* h_prev = (const float*)d_in[1];
    const float* c_prev = (const float*)d_in[2];
    const float* Wx     = (const float*)d_in[3];
    const float* Wxg    = (const float*)d_in[4];
    const float* tau    = (const float*)d_in[5];
    const float* Wq     = (const float*)d_in[6];
    const float* Wk     = (const float*)d_in[7];
    const float* Wv     = (const float*)d_in[8];
    const float* Wa_i   = (const float*)d_in[9];
    const float* Wxh_i  = (const float*)d_in[10];
    const float* b_i    = (const float*)d_in[11];
    const float* Wa_f   = (const float*)d_in[12];
    const float* Wxh_f  = (const float*)d_in[13];
    const float* b_f    = (const float*)d_in[14];
    const float* Wa_g   = (const float*)d_in[15];
    const float* Wxh_g  = (const float*)d_in[16];
    const float* b_g    = (const float*)d_in[17];
    const float* Wa_o   = (const float*)d_in[18];
    const float* Wxh_o  = (const float*)d_in[19];
    const float* b_o    = (const float*)d_in[20];
    float* out = (float*)d_out;

    proj_kernel     <<<dim3(HW/32, NB), 256>>>(inp, h_prev, Wx, Wxg);
    conv_same_kernel<<<dim3(3, 20, NB*GG), 128>>>(Wq, Wxh_i, Wxh_f, Wxh_g, Wxh_o);
    conv_kv_kernel  <<<dim3(3, 8, NB*GG), 128>>>(Wk, Wv);
    attn_kernel     <<<dim3(HW/8, NB*GG), 256>>>(tau);
    lstm_kernel     <<<dim3(HW/8, NB), 256>>>(Wa_i, Wa_f, Wa_g, Wa_o,
                                              b_i, b_f, b_g, b_o, c_prev, out);
}

// round 5
// speedup vs baseline: 2.6328x; 2.0271x over previous
#include <cuda_runtime.h>
#include <cuda_fp16.h>
#include <math.h>
#include <stdint.h>

// Problem constants
#define NB   4
#define CI   64
#define CC   256
#define GG   8
#define CG   32
#define KK   9
#define HH   48
#define WW   48
#define HW   (HH*WW)   // 2304
#define HD   40
#define WD   40
#define DD   (HD*WD)   // 1600
#define C2   (2*CC)
#define CPG  64        // 2C/G
#define STRIDE_GATE (NB*CC*HW)

typedef unsigned long long u64;

// Scratch (static device globals; allocation-free rule)
__device__ __half   g_xh16[NB*GG*HW*CPG];              // fp16 [n][g][pos][ci]
__device__ uint32_t g_wfrag[7*GG*81*16*32*2];          // B frags [conv][g][tap][ks*4+ns][lane][2]
__device__ float    g_q  [NB*CC*HW];
__device__ float    g_k  [NB*CC*DD];
__device__ float    g_v  [NB*CC*DD];
__device__ float    g_a  [NB*CC*HW];
__device__ float    g_gate[4*STRIDE_GATE];

// ---------------------------------------------------------------------------
// mma.sync helpers (compute_103-legal: no arch-suffix features)
// ---------------------------------------------------------------------------
__device__ __forceinline__ uint32_t smem_u32(const void* p) {
    uint32_t a;
    asm("{ .reg .u64 t; cvta.to.shared.u64 t, %1; cvt.u32.u64 %0, t; }"
        : "=r"(a) : "l"(p));
    return a;
}

__device__ __forceinline__ void ldmatrix_x4(uint32_t& r0, uint32_t& r1,
                                            uint32_t& r2, uint32_t& r3,
                                            uint32_t addr) {
    asm volatile("ldmatrix.sync.aligned.m8n8.x4.shared.b16 {%0,%1,%2,%3}, [%4];"
                 : "=r"(r0), "=r"(r1), "=r"(r2), "=r"(r3) : "r"(addr));
}

__device__ __forceinline__ void mma16816(float* c, uint32_t a0, uint32_t a1,
                                         uint32_t a2, uint32_t a3,
                                         uint32_t b0, uint32_t b1) {
    asm volatile("mma.sync.aligned.m16n8k16.row.col.f32.f16.f16.f32 "
                 "{%0,%1,%2,%3}, {%4,%5,%6,%7}, {%8,%9}, {%0,%1,%2,%3};"
                 : "+f"(c[0]), "+f"(c[1]), "+f"(c[2]), "+f"(c[3])
                 : "r"(a0), "r"(a1), "r"(a2), "r"(a3), "r"(b0), "r"(b1));
}

// ---------------------------------------------------------------------------
// Weight prep: build m16n8k16 B-fragments (col-major K x N = ci x oc).
// lane l holds b0 = {B[k0+(l%4)*2][n=l/4], B[k0+(l%4)*2+1][..]}, b1 = k0+8,
// where k0 = ks*16, n-tile base = ns*8.
// Layout: g_wfrag[(((conv*8+g)*81+t)*16 + ks*4+ns)*64 + lane*2 + {0,1}]
// ---------------------------------------------------------------------------
__global__ __launch_bounds__(256) void prep_wfrag(
    const float* __restrict__ Wq, const float* __restrict__ Wi,
    const float* __restrict__ Wf, const float* __restrict__ Wg2,
    const float* __restrict__ Wo, const float* __restrict__ Wk,
    const float* __restrict__ Wv)
{
    int idx = blockIdx.x * 256 + threadIdx.x;       // total 7*8*81*4*4*32 = 2322432
    int conv = idx / 331776;
    int rem  = idx - conv * 331776;
    int g    = rem / 41472;  rem -= g * 41472;
    int t    = rem >> 9;     rem &= 511;
    int ks   = rem >> 7;
    int ns   = (rem >> 5) & 3;
    int lane = rem & 31;

    const float* W = (conv == 0) ? Wq : (conv == 1) ? Wi : (conv == 2) ? Wf :
                     (conv == 3) ? Wg2 : (conv == 4) ? Wo : (conv == 5) ? Wk : Wv;

    int oc  = ns*8 + (lane >> 2);
    int ci0 = ks*16 + (lane & 3)*2;
    const float* wb = W + (size_t)(g*32 + oc)*5184 + t;   // [oc][ci][81]

    __half2 h0 = __floats2half2_rn(wb[(ci0    )*81], wb[(ci0 + 1)*81]);
    __half2 h1 = __floats2half2_rn(wb[(ci0 + 8)*81], wb[(ci0 + 9)*81]);

    uint32_t* outp = g_wfrag + (size_t)((((conv*8 + g)*81 + t)*16 + ks*4 + ns)*32 + lane)*2;
    outp[0] = *reinterpret_cast<uint32_t*>(&h0);
    outp[1] = *reinterpret_cast<uint32_t*>(&h1);
}

// ---------------------------------------------------------------------------
// Kernel 1: proj — x = Wx*inp + Wxg*h; writes fp16 interleaved [n][g][pos][ci]
// ---------------------------------------------------------------------------
__global__ __launch_bounds__(256) void proj_kernel(
    const float* __restrict__ inp, const float* __restrict__ h,
    const float* __restrict__ Wx,  const float* __restrict__ Wxg)
{
    __shared__ float s_in[CI][32];
    __shared__ float s_h [CC][32];
    const int n  = blockIdx.y;
    const int p0 = blockIdx.x * 32;
    const int t  = threadIdx.x;

    for (int i = t; i < CI*32; i += 256) {
        int ch = i >> 5, p = i & 31;
        s_in[ch][p] = inp[(n*CI + ch)*HW + p0 + p];
    }
    for (int i = t; i < CC*32; i += 256) {
        int ch = i >> 5, p = i & 31;
        s_h[ch][p] = h[(n*CC + ch)*HW + p0 + p];
    }
    __syncthreads();

    const int c = t, g = c >> 5, cg = c & 31;
    float acc[32];
    #pragma unroll
    for (int p = 0; p < 32; p++) acc[p] = 0.f;

    const float4* wx4 = reinterpret_cast<const float4*>(Wx + c*CI);
    for (int ci4 = 0; ci4 < CI/4; ci4++) {
        float4 w = wx4[ci4];
        int cb = ci4 * 4;
        #pragma unroll
        for (int p = 0; p < 32; p++)
            acc[p] += w.x*s_in[cb][p] + w.y*s_in[cb+1][p]
                    + w.z*s_in[cb+2][p] + w.w*s_in[cb+3][p];
    }
    const float4* wg4 = reinterpret_cast<const float4*>(Wxg + c*CC);
    for (int ci4 = 0; ci4 < CC/4; ci4++) {
        float4 w = wg4[ci4];
        int cb = ci4 * 4;
        #pragma unroll
        for (int p = 0; p < 32; p++)
            acc[p] += w.x*s_h[cb][p] + w.y*s_h[cb+1][p]
                    + w.z*s_h[cb+2][p] + w.w*s_h[cb+3][p];
    }
    __half* x16 = g_xh16 + ((size_t)(n*GG + g)*HW + p0)*CPG;
    #pragma unroll
    for (int p = 0; p < 32; p++) {
        x16[(size_t)p*CPG + cg]      = __float2half(acc[p]);
        x16[(size_t)p*CPG + 32 + cg] = __float2half(s_h[c][p]);
    }
}

// ---------------------------------------------------------------------------
// Implicit-GEMM grouped 9x9 conv via mma.sync.
// CTA: 128 thr (4 warps), out tile 8 rows x 16 cols.
// M-index m = j*24 + x (x<16 valid); per tap, A-row = tile[m + ky*24 + kx].
// Input tile: 16 rows x 24 cols, 144B stride (400 slots incl. pad overrun).
// B: per-tap 4KB fragment block staged through SMEM.
// ---------------------------------------------------------------------------
#define TILE_SLOTS 400
#define SM_BOFF    (TILE_SLOTS*144)                 // 57600
#define SMT_CONV   (SM_BOFF + 4096)                 // 61696 bytes

template<int OUTH, int OUTW, int PAD>
__device__ __forceinline__ void conv_mma_body(
    const __half* __restrict__ xin,        // [HW][64] fp16 for (n,g)
    const uint32_t* __restrict__ bfrag,    // [81][16][32][2] for (conv,g)
    float* __restrict__ outp,              // base for oc0=0 plane, stride OUTH*OUTW
    int y0, int x0)
{
    extern __shared__ char smem[];
    const uint32_t s_tile = smem_u32(smem);
    const int tid = threadIdx.x, wid = tid >> 5, lane = tid & 31;

    // Load input tile (16 rows x 24 cols), zero-guarded; fill pad slots too.
    for (int i = tid; i < TILE_SLOTS*8; i += 128) {
        int pos = i >> 3, sub = i & 7;
        int rr = pos / 24, cc = pos - rr*24;
        int gy = y0 + rr - PAD, gx = x0 + cc - PAD;
        uint4 v = make_uint4(0u, 0u, 0u, 0u);
        if (gy >= 0 && gy < HH && gx >= 0 && gx < WW)
            v = *reinterpret_cast<const uint4*>(xin + ((size_t)(gy*WW + gx) << 6) + (sub << 3));
        *reinterpret_cast<uint4*>(smem + pos*144 + sub*16) = v;
    }

    float acc[3][4][4];
    #pragma unroll
    for (int ss = 0; ss < 3; ss++)
        #pragma unroll
        for (int nt = 0; nt < 4; nt++)
            #pragma unroll
            for (int r = 0; r < 4; r++) acc[ss][nt][r] = 0.f;

    // ldmatrix lane address components (row within 16, k-halfword offset)
    const int lrow = (lane & 7) + ((lane >> 3) & 1)*8;
    const int lkb  = ((lane >> 4) & 1)*16;

    for (int t = 0; t < 81; t++) {
        __syncthreads();
        // stage B fragments for this tap: 4KB
        {
            const uint4* bs = reinterpret_cast<const uint4*>(bfrag + t*1024);
            uint4* bd = reinterpret_cast<uint4*>(smem + SM_BOFF);
            bd[tid]       = bs[tid];
            bd[tid + 128] = bs[tid + 128];
        }
        __syncthreads();

        const int tap_off = (t/9)*24 + (t%9);
        #pragma unroll
        for (int ks = 0; ks < 4; ks++) {
            // B frags for 4 n-tiles
            uint32_t b[4][2];
            #pragma unroll
            for (int nt = 0; nt < 4; nt++) {
                u64 v = *reinterpret_cast<const u64*>(
                    smem + SM_BOFF + ((ks*4 + nt)*32 + lane)*8);
                b[nt][0] = (uint32_t)v;
                b[nt][1] = (uint32_t)(v >> 32);
            }
            #pragma unroll
            for (int ss = 0; ss < 3; ss++) {
                const int pbase = (ss*4 + wid)*16 + tap_off;
                uint32_t a0, a1, a2, a3;
                ldmatrix_x4(a0, a1, a2, a3,
                            s_tile + (uint32_t)(pbase + lrow)*144 + (uint32_t)(ks*32 + lkb));
                #pragma unroll
                for (int nt = 0; nt < 4; nt++)
                    mma16816(acc[ss][nt], a0, a1, a2, a3, b[nt][0], b[nt][1]);
            }
        }
    }

    // Store: lane holds C rows r=lane/4 (+8), cols (lane%4)*2 (+1), per n-tile.
    const int r  = lane >> 2;
    const int cp = (lane & 3)*2;
    #pragma unroll
    for (int ss = 0; ss < 3; ss++) {
        const int mbase = (ss*4 + wid)*16;
        #pragma unroll
        for (int half = 0; half < 2; half++) {
            int m = mbase + r + half*8;
            int j = m / 24, x = m - j*24;
            if (x < 16) {
                int ox = x0 + x;
                if (ox < OUTW) {
                    int off = (y0 + j)*OUTW + ox;
                    #pragma unroll
                    for (int nt = 0; nt < 4; nt++) {
                        int oc = nt*8 + cp;
                        outp[(size_t)oc*OUTH*OUTW + off]       = acc[ss][nt][half*2];
                        outp[(size_t)(oc+1)*OUTH*OUTW + off]   = acc[ss][nt][half*2+1];
                    }
                }
            }
        }
    }
}

// SAME convs: q + 4 gates. grid (18, 5, 32): x = tile (6 rows x 3 cols)
__global__ __launch_bounds__(128) void conv_same_mma()
{
    const int n = blockIdx.z >> 3, g = blockIdx.z & 7;
    const int conv = blockIdx.y;
    const int ty = blockIdx.x / 3, tx = blockIdx.x - ty*3;
    float* outp = (conv == 0)
        ? g_q + (size_t)(n*CC + g*CG)*HW
        : g_gate + (size_t)(conv-1)*STRIDE_GATE + (size_t)(n*CC + g*CG)*HW;
    conv_mma_body<HH, WW, 4>(
        g_xh16 + (size_t)(n*GG + g)*HW*CPG,
        g_wfrag + (size_t)(conv*GG + g)*81*1024,
        outp, ty*8, tx*16);
}

// VALID convs: k, v. grid (15, 2, 32): x = tile (5 rows x 3 cols)
__global__ __launch_bounds__(128) void conv_valid_mma()
{
    const int n = blockIdx.z >> 3, g = blockIdx.z & 7;
    const int sel = blockIdx.y;                     // 0=k, 1=v
    const int ty = blockIdx.x / 3, tx = blockIdx.x - ty*3;
    float* outp = (sel ? g_v : g_k) + (size_t)(n*CC + g*CG)*DD;
    conv_mma_body<HD, WD, 0>(
        g_xh16 + (size_t)(n*GG + g)*HW*CPG,
        g_wfrag + (size_t)((5 + sel)*GG + g)*81*1024,
        outp, ty*8, tx*16);
}

// ---------------------------------------------------------------------------
// Kernel 3: attention (unchanged this round)
// ---------------------------------------------------------------------------
__global__ __launch_bounds__(256) void attn_kernel(const float* __restrict__ tau)
{
    __shared__ float s_kv[CG][320];
    __shared__ float s_q [8][CG];
    const int ngi = blockIdx.y;
    const int n = ngi >> 3, g = ngi & 7;
    const int r0 = blockIdx.x * 8;
    const int t = threadIdx.x, warp = t >> 5, lane = t & 31;

    for (int i = t; i < 8*CG; i += 256) {
        int r = i >> 5, c = i & 31;
        s_q[r][c] = g_q[((size_t)(n*CC + g*CG + c))*HW + r0 + r];
    }

    float sc[50];
    #pragma unroll
    for (int ch = 0; ch < 5; ch++) {
        __syncthreads();
        for (int i = t; i < CG*320; i += 256) {
            int c = i / 320, dd = i - c*320;
            s_kv[c][dd] = g_k[((size_t)(n*CC + g*CG + c))*DD + ch*320 + dd];
        }
        __syncthreads();
        float accd[10];
        #pragma unroll
        for (int j = 0; j < 10; j++) accd[j] = 0.f;
        for (int c = 0; c < CG; c++) {
            float qv = s_q[warp][c];
            #pragma unroll
            for (int j = 0; j < 10; j++)
                accd[j] = fmaf(qv, s_kv[c][lane + 32*j], accd[j]);
        }
        #pragma unroll
        for (int j = 0; j < 10; j++) sc[ch*10 + j] = accd[j];
    }

    const float tg = tau[g];
    float m = -1e30f;
    #pragma unroll
    for (int j = 0; j < 50; j++) { sc[j] *= tg; m = fmaxf(m, sc[j]); }
    #pragma unroll
    for (int o = 16; o > 0; o >>= 1)
        m = fmaxf(m, __shfl_xor_sync(0xffffffffu, m, o));
    float s = 0.f;
    #pragma unroll
    for (int j = 0; j < 50; j++) { sc[j] = __expf(sc[j] - m); s += sc[j]; }
    #pragma unroll
    for (int o = 16; o > 0; o >>= 1)
        s += __shfl_xor_sync(0xffffffffu, s, o);
    const float inv = 1.f / s;
    #pragma unroll
    for (int j = 0; j < 50; j++) sc[j] *= inv;

    float acco[CG];
    #pragma unroll
    for (int c = 0; c < CG; c++) acco[c] = 0.f;
    #pragma unroll
    for (int ch = 0; ch < 5; ch++) {
        __syncthreads();
        for (int i = t; i < CG*320; i += 256) {
            int c = i / 320, dd = i - c*320;
            s_kv[c][dd] = g_v[((size_t)(n*CC + g*CG + c))*DD + ch*320 + dd];
        }
        __syncthreads();
        #pragma unroll
        for (int j = 0; j < 10; j++) {
            float pv = sc[ch*10 + j];
            #pragma unroll
            for (int c = 0; c < CG; c++)
                acco[c] = fmaf(pv, s_kv[c][lane + 32*j], acco[c]);
        }
    }

    float myout = 0.f;
    #pragma unroll
    for (int c = 0; c < CG; c++) {
        float v = acco[c];
        #pragma unroll
        for (int o = 16; o > 0; o >>= 1)
            v += __shfl_xor_sync(0xffffffffu, v, o);
        if (lane == c) myout = v;
    }
    g_a[((size_t)(n*CC + g*CG + lane))*HW + r0 + warp] = myout;
}

// ---------------------------------------------------------------------------
// Kernel 4: LSTM epilogue (unchanged)
// ---------------------------------------------------------------------------
__device__ __forceinline__ float sigmoidf_(float x) { return 1.f / (1.f + __expf(-x)); }

__global__ __launch_bounds__(256) void lstm_kernel(
    const float* __restrict__ Wa0, const float* __restrict__ Wa1,
    const float* __restrict__ Wa2, const float* __restrict__ Wa3,
    const float* __restrict__ b0,  const float* __restrict__ b1,
    const float* __restrict__ b2,  const float* __restrict__ b3,
    const float* __restrict__ c_prev, float* __restrict__ out)
{
    __shared__ float s_a[CC][8];
    const int n  = blockIdx.y;
    const int p0 = blockIdx.x * 8;
    const int t  = threadIdx.x;

    for (int i = t; i < CC*8; i += 256) {
        int ch = i >> 3, p = i & 7;
        s_a[ch][p] = g_a[((size_t)(n*CC + ch))*HW + p0 + p];
    }
    __syncthreads();

    const int c = t, g = c >> 5;
    float a0[8], a1[8], a2[8], a3[8];
    #pragma unroll
    for (int p = 0; p < 8; p++) { a0[p] = a1[p] = a2[p] = a3[p] = 0.f; }

    const float* wa0 = Wa0 + c*CG;
    const float* wa1 = Wa1 + c*CG;
    const float* wa2 = Wa2 + c*CG;
    const float* wa3 = Wa3 + c*CG;
    for (int cg = 0; cg < CG; cg++) {
        float w0 = wa0[cg], w1 = wa1[cg], w2 = wa2[cg], w3 = wa3[cg];
        const float* ar = s_a[g*CG + cg];
        #pragma unroll
        for (int p = 0; p < 8; p++) {
            float av = ar[p];
            a0[p] = fmaf(w0, av, a0[p]);
            a1[p] = fmaf(w1, av, a1[p]);
            a2[p] = fmaf(w2, av, a2[p]);
            a3[p] = fmaf(w3, av, a3[p]);
        }
    }

    const float bi = b0[c], bf = b1[c], bg = b2[c], bo = b3[c];
    const int idx0 = (n*CC + c)*HW + p0;
    #pragma unroll
    for (int p = 0; p < 8; p++) {
        int idx = idx0 + p;
        float gi = sigmoidf_(a0[p] + g_gate[                 idx] + bi);
        float gf = sigmoidf_(a1[p] + g_gate[  STRIDE_GATE  + idx] + bf);
        float gg = tanhf    (a2[p] + g_gate[2*STRIDE_GATE  + idx] + bg);
        float go = sigmoidf_(a3[p] + g_gate[3*STRIDE_GATE  + idx] + bo);
        float cn = gf * c_prev[idx] + gi * gg;
        out[idx] = go * tanhf(cn);
    }
}

// ---------------------------------------------------------------------------
extern "C" void kernel_launch(void* const* d_in, const int* in_sizes, int n_in,
                              void* d_out, int out_size)
{
    const float* inp    = (const float*)d_in[0];
    const float* h_prev = (const float*)d_in[1];
    const float* c_prev = (const float*)d_in[2];
    const float* Wx     = (const float*)d_in[3];
    const float* Wxg    = (const float*)d_in[4];
    const float* tau    = (const float*)d_in[5];
    const float* Wq     = (const float*)d_in[6];
    const float* Wk     = (const float*)d_in[7];
    const float* Wv     = (const float*)d_in[8];
    const float* Wa_i   = (const float*)d_in[9];
    const float* Wxh_i  = (const float*)d_in[10];
    const float* b_i    = (const float*)d_in[11];
    const float* Wa_f   = (const float*)d_in[12];
    const float* Wxh_f  = (const float*)d_in[13];
    const float* b_f    = (const float*)d_in[14];
    const float* Wa_g   = (const float*)d_in[15];
    const float* Wxh_g  = (const float*)d_in[16];
    const float* b_g    = (const float*)d_in[17];
    const float* Wa_o   = (const float*)d_in[18];
    const float* Wxh_o  = (const float*)d_in[19];
    const float* b_o    = (const float*)d_in[20];
    float* out = (float*)d_out;

    cudaFuncSetAttribute(conv_same_mma,
                         cudaFuncAttributeMaxDynamicSharedMemorySize, SMT_CONV);
    cudaFuncSetAttribute(conv_valid_mma,
                         cudaFuncAttributeMaxDynamicSharedMemorySize, SMT_CONV);

    prep_wfrag      <<<9072, 256>>>(Wq, Wxh_i, Wxh_f, Wxh_g, Wxh_o, Wk, Wv);
    proj_kernel     <<<dim3(HW/32, NB), 256>>>(inp, h_prev, Wx, Wxg);
    conv_same_mma   <<<dim3(18, 5, NB*GG), 128, SMT_CONV>>>();
    conv_valid_mma  <<<dim3(15, 2, NB*GG), 128, SMT_CONV>>>();
    attn_kernel     <<<dim3(HW/8, NB*GG), 256>>>(tau);
    lstm_kernel     <<<dim3(HW/8, NB), 256>>>(Wa_i, Wa_f, Wa_g, Wa_o,
                                              b_i, b_f, b_g, b_o, c_prev, out);
}

// round 6
// speedup vs baseline: 5.7832x; 2.1966x over previous
#include <cuda_runtime.h>
#include <cuda_fp16.h>
#include <math.h>
#include <stdint.h>

// Problem constants
#define NB   4
#define CI   64
#define CC   256
#define GG   8
#define CG   32
#define KK   9
#define HH   48
#define WW   48
#define HW   (HH*WW)   // 2304
#define HD   40
#define WD   40
#define DD   (HD*WD)   // 1600
#define C2   (2*CC)
#define CPG  64        // 2C/G
#define STRIDE_GATE (NB*CC*HW)

typedef unsigned long long u64;

// Scratch (static device globals; allocation-free rule)
__device__ __half   g_xh16[NB*GG*HW*CPG];              // fp16 [n][g][pos][ci]
__device__ uint32_t g_wfrag[7*GG*81*16*32*2];          // B frags [conv][g][tap][ks*4+ns][lane][2]
__device__ __half   g_q16 [NB*GG*HW*CG];               // q*tau  fp16 [n][g][pos][32]
__device__ __half   g_k16 [NB*GG*DD*CG];               // k      fp16 [n][g][key][32]
__device__ __half   g_v16 [NB*GG*CG*DD];               // v      fp16 [n][g][ch][key]
__device__ float    g_a   [NB*CC*HW];
__device__ float    g_gate[4*STRIDE_GATE];

// ---------------------------------------------------------------------------
// mma.sync helpers (compute_103-legal)
// ---------------------------------------------------------------------------
__device__ __forceinline__ uint32_t smem_u32(const void* p) {
    uint32_t a;
    asm("{ .reg .u64 t; cvta.to.shared.u64 t, %1; cvt.u32.u64 %0, t; }"
        : "=r"(a) : "l"(p));
    return a;
}

__device__ __forceinline__ void ldmatrix_x4(uint32_t& r0, uint32_t& r1,
                                            uint32_t& r2, uint32_t& r3,
                                            uint32_t addr) {
    asm volatile("ldmatrix.sync.aligned.m8n8.x4.shared.b16 {%0,%1,%2,%3}, [%4];"
                 : "=r"(r0), "=r"(r1), "=r"(r2), "=r"(r3) : "r"(addr));
}

__device__ __forceinline__ void mma16816(float* c, uint32_t a0, uint32_t a1,
                                         uint32_t a2, uint32_t a3,
                                         uint32_t b0, uint32_t b1) {
    asm volatile("mma.sync.aligned.m16n8k16.row.col.f32.f16.f16.f32 "
                 "{%0,%1,%2,%3}, {%4,%5,%6,%7}, {%8,%9}, {%0,%1,%2,%3};"
                 : "+f"(c[0]), "+f"(c[1]), "+f"(c[2]), "+f"(c[3])
                 : "r"(a0), "r"(a1), "r"(a2), "r"(a3), "r"(b0), "r"(b1));
}

__device__ __forceinline__ uint32_t pack_h2(float a, float b) {
    __half2 h = __floats2half2_rn(a, b);
    return *reinterpret_cast<uint32_t*>(&h);
}

// ---------------------------------------------------------------------------
// Weight prep: build m16n8k16 B-fragments (unchanged)
// ---------------------------------------------------------------------------
__global__ __launch_bounds__(256) void prep_wfrag(
    const float* __restrict__ Wq, const float* __restrict__ Wi,
    const float* __restrict__ Wf, const float* __restrict__ Wg2,
    const float* __restrict__ Wo, const float* __restrict__ Wk,
    const float* __restrict__ Wv)
{
    int idx = blockIdx.x * 256 + threadIdx.x;
    int conv = idx / 331776;
    int rem  = idx - conv * 331776;
    int g    = rem / 41472;  rem -= g * 41472;
    int t    = rem >> 9;     rem &= 511;
    int ks   = rem >> 7;
    int ns   = (rem >> 5) & 3;
    int lane = rem & 31;

    const float* W = (conv == 0) ? Wq : (conv == 1) ? Wi : (conv == 2) ? Wf :
                     (conv == 3) ? Wg2 : (conv == 4) ? Wo : (conv == 5) ? Wk : Wv;

    int oc  = ns*8 + (lane >> 2);
    int ci0 = ks*16 + (lane & 3)*2;
    const float* wb = W + (size_t)(g*32 + oc)*5184 + t;

    __half2 h0 = __floats2half2_rn(wb[(ci0    )*81], wb[(ci0 + 1)*81]);
    __half2 h1 = __floats2half2_rn(wb[(ci0 + 8)*81], wb[(ci0 + 9)*81]);

    uint32_t* outp = g_wfrag + (size_t)((((conv*8 + g)*81 + t)*16 + ks*4 + ns)*32 + lane)*2;
    outp[0] = *reinterpret_cast<uint32_t*>(&h0);
    outp[1] = *reinterpret_cast<uint32_t*>(&h1);
}

// ---------------------------------------------------------------------------
// Kernel 1: proj (unchanged) — writes fp16 interleaved xh [n][g][pos][ci]
// ---------------------------------------------------------------------------
__global__ __launch_bounds__(256) void proj_kernel(
    const float* __restrict__ inp, const float* __restrict__ h,
    const float* __restrict__ Wx,  const float* __restrict__ Wxg)
{
    __shared__ float s_in[CI][32];
    __shared__ float s_h [CC][32];
    const int n  = blockIdx.y;
    const int p0 = blockIdx.x * 32;
    const int t  = threadIdx.x;

    for (int i = t; i < CI*32; i += 256) {
        int ch = i >> 5, p = i & 31;
        s_in[ch][p] = inp[(n*CI + ch)*HW + p0 + p];
    }
    for (int i = t; i < CC*32; i += 256) {
        int ch = i >> 5, p = i & 31;
        s_h[ch][p] = h[(n*CC + ch)*HW + p0 + p];
    }
    __syncthreads();

    const int c = t, g = c >> 5, cg = c & 31;
    float acc[32];
    #pragma unroll
    for (int p = 0; p < 32; p++) acc[p] = 0.f;

    const float4* wx4 = reinterpret_cast<const float4*>(Wx + c*CI);
    for (int ci4 = 0; ci4 < CI/4; ci4++) {
        float4 w = wx4[ci4];
        int cb = ci4 * 4;
        #pragma unroll
        for (int p = 0; p < 32; p++)
            acc[p] += w.x*s_in[cb][p] + w.y*s_in[cb+1][p]
                    + w.z*s_in[cb+2][p] + w.w*s_in[cb+3][p];
    }
    const float4* wg4 = reinterpret_cast<const float4*>(Wxg + c*CC);
    for (int ci4 = 0; ci4 < CC/4; ci4++) {
        float4 w = wg4[ci4];
        int cb = ci4 * 4;
        #pragma unroll
        for (int p = 0; p < 32; p++)
            acc[p] += w.x*s_h[cb][p] + w.y*s_h[cb+1][p]
                    + w.z*s_h[cb+2][p] + w.w*s_h[cb+3][p];
    }
    __half* x16 = g_xh16 + ((size_t)(n*GG + g)*HW + p0)*CPG;
    #pragma unroll
    for (int p = 0; p < 32; p++) {
        x16[(size_t)p*CPG + cg]      = __float2half(acc[p]);
        x16[(size_t)p*CPG + 32 + cg] = __float2half(s_h[c][p]);
    }
}

// ---------------------------------------------------------------------------
// Implicit-GEMM grouped 9x9 conv via mma.sync.
// B fragments read directly from global (L1-resident, warp-uniform) — no
// per-tap staging, no per-tap syncs.
// Store modes: 0 = fp32 planar; 1 = fp16 [pos][32] *scale (q); 2 = fp16
// [pos][32] (k); 3 = fp16 planar [ch][pos] (v).
// ---------------------------------------------------------------------------
#define TILE_SLOTS 400
#define SMT_CONV   (TILE_SLOTS*144)   // 57600 bytes

template<int OUTH, int OUTW, int PAD, int MODE>
__device__ __forceinline__ void conv_mma_body(
    const __half* __restrict__ xin,
    const uint32_t* __restrict__ bfrag,
    void* __restrict__ outv,
    int y0, int x0, float scale)
{
    extern __shared__ char smem[];
    const uint32_t s_tile = smem_u32(smem);
    const int tid = threadIdx.x, wid = tid >> 5, lane = tid & 31;

    for (int i = tid; i < TILE_SLOTS*8; i += 128) {
        int pos = i >> 3, sub = i & 7;
        int rr = pos / 24, cc = pos - rr*24;
        int gy = y0 + rr - PAD, gx = x0 + cc - PAD;
        uint4 v = make_uint4(0u, 0u, 0u, 0u);
        if (gy >= 0 && gy < HH && gx >= 0 && gx < WW)
            v = *reinterpret_cast<const uint4*>(xin + ((size_t)(gy*WW + gx) << 6) + (sub << 3));
        *reinterpret_cast<uint4*>(smem + pos*144 + sub*16) = v;
    }
    __syncthreads();

    float acc[3][4][4];
    #pragma unroll
    for (int ss = 0; ss < 3; ss++)
        #pragma unroll
        for (int nt = 0; nt < 4; nt++)
            #pragma unroll
            for (int r = 0; r < 4; r++) acc[ss][nt][r] = 0.f;

    const int lrow = (lane & 7) + ((lane >> 3) & 1)*8;
    const int lkb  = ((lane >> 4) & 1)*16;

    for (int t = 0; t < 81; t++) {
        const uint32_t* bt = bfrag + t*1024 + lane*2;
        const int tap_off = (t/9)*24 + (t%9);
        #pragma unroll
        for (int ks = 0; ks < 4; ks++) {
            uint32_t b[4][2];
            #pragma unroll
            for (int nt = 0; nt < 4; nt++) {
                u64 v = __ldg(reinterpret_cast<const u64*>(bt + (ks*4 + nt)*64));
                b[nt][0] = (uint32_t)v;
                b[nt][1] = (uint32_t)(v >> 32);
            }
            #pragma unroll
            for (int ss = 0; ss < 3; ss++) {
                const int pbase = (ss*4 + wid)*16 + tap_off;
                uint32_t a0, a1, a2, a3;
                ldmatrix_x4(a0, a1, a2, a3,
                            s_tile + (uint32_t)(pbase + lrow)*144 + (uint32_t)(ks*32 + lkb));
                #pragma unroll
                for (int nt = 0; nt < 4; nt++)
                    mma16816(acc[ss][nt], a0, a1, a2, a3, b[nt][0], b[nt][1]);
            }
        }
    }

    const int r  = lane >> 2;
    const int cp = (lane & 3)*2;
    #pragma unroll
    for (int ss = 0; ss < 3; ss++) {
        const int mbase = (ss*4 + wid)*16;
        #pragma unroll
        for (int half = 0; half < 2; half++) {
            int m = mbase + r + half*8;
            int j = m / 24, x = m - j*24;
            if (x < 16) {
                int ox = x0 + x;
                if (ox < OUTW) {
                    int off = (y0 + j)*OUTW + ox;
                    #pragma unroll
                    for (int nt = 0; nt < 4; nt++) {
                        int oc = nt*8 + cp;
                        float v0 = acc[ss][nt][half*2];
                        float v1 = acc[ss][nt][half*2+1];
                        if (MODE == 0) {
                            float* o = (float*)outv;
                            o[(size_t)oc*OUTH*OUTW + off]     = v0;
                            o[(size_t)(oc+1)*OUTH*OUTW + off] = v1;
                        } else if (MODE == 1 || MODE == 2) {
                            __half* o = (__half*)outv;
                            __half2 h = __floats2half2_rn(v0*scale, v1*scale);
                            *reinterpret_cast<__half2*>(o + (size_t)off*32 + oc) = h;
                        } else {
                            __half* o = (__half*)outv;
                            o[(size_t)oc*OUTH*OUTW + off]     = __float2half(v0);
                            o[(size_t)(oc+1)*OUTH*OUTW + off] = __float2half(v1);
                        }
                    }
                }
            }
        }
    }
}

// SAME convs: q + 4 gates. grid (18, 5, 32)
__global__ __launch_bounds__(128) void conv_same_mma(const float* __restrict__ tau)
{
    const int n = blockIdx.z >> 3, g = blockIdx.z & 7;
    const int conv = blockIdx.y;
    const int ty = blockIdx.x / 3, tx = blockIdx.x - ty*3;
    const __half* xin = g_xh16 + (size_t)(n*GG + g)*HW*CPG;
    const uint32_t* bf = g_wfrag + (size_t)(conv*GG + g)*81*1024;
    if (conv == 0) {
        conv_mma_body<HH, WW, 4, 1>(xin, bf,
            g_q16 + (size_t)(n*GG + g)*HW*CG, ty*8, tx*16, tau[g]);
    } else {
        conv_mma_body<HH, WW, 4, 0>(xin, bf,
            g_gate + (size_t)(conv-1)*STRIDE_GATE + (size_t)(n*CC + g*CG)*HW,
            ty*8, tx*16, 1.f);
    }
}

// VALID convs: k, v. grid (15, 2, 32)
__global__ __launch_bounds__(128) void conv_valid_mma()
{
    const int n = blockIdx.z >> 3, g = blockIdx.z & 7;
    const int sel = blockIdx.y;
    const int ty = blockIdx.x / 3, tx = blockIdx.x - ty*3;
    const __half* xin = g_xh16 + (size_t)(n*GG + g)*HW*CPG;
    const uint32_t* bf = g_wfrag + (size_t)((5 + sel)*GG + g)*81*1024;
    if (sel == 0) {
        conv_mma_body<HD, WD, 0, 2>(xin, bf,
            g_k16 + (size_t)(n*GG + g)*DD*CG, ty*8, tx*16, 1.f);
    } else {
        conv_mma_body<HD, WD, 0, 3>(xin, bf,
            g_v16 + (size_t)(n*GG + g)*CG*DD, ty*8, tx*16, 1.f);
    }
}

// ---------------------------------------------------------------------------
// Kernel 3: flash-style mma attention.
// grid (36, 32), block 128 (4 warps). CTA = 64 query rows; 25 key-chunks of 64.
// S = Q*K^T (tau pre-folded into q), online softmax in C-fragments,
// P (fp16, in-register C->A relayout) @ V into O fragments.
// ---------------------------------------------------------------------------
__global__ __launch_bounds__(128) void attn_mma()
{
    __shared__ __align__(16) char s_q[64*80];
    __shared__ __align__(16) char s_k[64*80];
    __shared__ __align__(16) char s_v[32*144];
    const int tid = threadIdx.x, wid = tid >> 5, lane = tid & 31;
    const int n = blockIdx.y >> 3, g = blockIdx.y & 7;
    const int q0 = blockIdx.x * 64;

    const __half* qsrc = g_q16 + (size_t)(n*GG + g)*HW*CG;
    const __half* ksrc = g_k16 + (size_t)(n*GG + g)*DD*CG;
    const __half* vsrc = g_v16 + (size_t)(n*GG + g)*CG*DD;

    // Load Q tile: 64 rows x 64B, smem stride 80B (conflict-free ldmatrix)
    for (int i = tid; i < 256; i += 128) {
        int row = i >> 2, sub = i & 3;
        *reinterpret_cast<uint4*>(s_q + row*80 + sub*16) =
            *reinterpret_cast<const uint4*>(
                reinterpret_cast<const char*>(qsrc + (size_t)(q0 + row)*32) + sub*16);
    }
    __syncthreads();

    // Q A-fragments (row-major m16k16, 2 k-slices of 16 ch)
    const int m0 = wid*16;
    uint32_t aq[2][4];
    #pragma unroll
    for (int ks = 0; ks < 2; ks++) {
        uint32_t addr = smem_u32(s_q) + (uint32_t)(m0 + (lane & 15))*80
                      + (uint32_t)(ks*32 + (lane >> 4)*16);
        ldmatrix_x4(aq[ks][0], aq[ks][1], aq[ks][2], aq[ks][3], addr);
    }

    float O[4][4];
    #pragma unroll
    for (int nt = 0; nt < 4; nt++)
        #pragma unroll
        for (int r = 0; r < 4; r++) O[nt][r] = 0.f;
    float mrun0 = -1e30f, mrun1 = -1e30f, lsum0 = 0.f, lsum1 = 0.f;

    const uint32_t sk = smem_u32(s_k), sv = smem_u32(s_v);

    for (int chn = 0; chn < 25; chn++) {
        const int d0 = chn*64;
        __syncthreads();
        // K chunk: 64 keys x 64B -> stride 80
        for (int i = tid; i < 256; i += 128) {
            int row = i >> 2, sub = i & 3;
            *reinterpret_cast<uint4*>(s_k + row*80 + sub*16) =
                *reinterpret_cast<const uint4*>(
                    reinterpret_cast<const char*>(ksrc + (size_t)(d0 + row)*32) + sub*16);
        }
        // V chunk: 32 ch x 128B -> stride 144
        for (int i = tid; i < 256; i += 128) {
            int row = i >> 3, sub = i & 7;
            *reinterpret_cast<uint4*>(s_v + row*144 + sub*16) =
                *reinterpret_cast<const uint4*>(
                    reinterpret_cast<const char*>(vsrc + (size_t)row*DD + d0) + sub*16);
        }
        __syncthreads();

        // S = Q K^T : 8 n-tiles (8 keys each) x 2 k-slices
        float sc[8][4];
        #pragma unroll
        for (int nt = 0; nt < 8; nt++)
            #pragma unroll
            for (int r = 0; r < 4; r++) sc[nt][r] = 0.f;
        #pragma unroll
        for (int ks = 0; ks < 2; ks++) {
            #pragma unroll
            for (int j = 0; j < 4; j++) {       // key-pair tiles (16 keys)
                uint32_t b0, b1, b2, b3;
                uint32_t addr = sk + (uint32_t)(j*16 + (lane & 7) + ((lane >> 4) & 1)*8)*80
                              + (uint32_t)(ks*32 + ((lane >> 3) & 1)*16);
                ldmatrix_x4(b0, b1, b2, b3, addr);
                mma16816(sc[2*j],   aq[ks][0], aq[ks][1], aq[ks][2], aq[ks][3], b0, b1);
                mma16816(sc[2*j+1], aq[ks][0], aq[ks][1], aq[ks][2], aq[ks][3], b2, b3);
            }
        }

        // Online softmax (rows r=lane/4 and r+8; group = 4 lanes, xor 1,2)
        float ml0 = -1e30f, ml1 = -1e30f;
        #pragma unroll
        for (int nt = 0; nt < 8; nt++) {
            ml0 = fmaxf(ml0, fmaxf(sc[nt][0], sc[nt][1]));
            ml1 = fmaxf(ml1, fmaxf(sc[nt][2], sc[nt][3]));
        }
        ml0 = fmaxf(ml0, __shfl_xor_sync(0xffffffffu, ml0, 1));
        ml0 = fmaxf(ml0, __shfl_xor_sync(0xffffffffu, ml0, 2));
        ml1 = fmaxf(ml1, __shfl_xor_sync(0xffffffffu, ml1, 1));
        ml1 = fmaxf(ml1, __shfl_xor_sync(0xffffffffu, ml1, 2));
        float mn0 = fmaxf(mrun0, ml0), mn1 = fmaxf(mrun1, ml1);
        float scl0 = __expf(mrun0 - mn0), scl1 = __expf(mrun1 - mn1);
        mrun0 = mn0; mrun1 = mn1;
        lsum0 *= scl0; lsum1 *= scl1;
        #pragma unroll
        for (int nt = 0; nt < 4; nt++) {
            O[nt][0] *= scl0; O[nt][1] *= scl0;
            O[nt][2] *= scl1; O[nt][3] *= scl1;
        }
        #pragma unroll
        for (int nt = 0; nt < 8; nt++) {
            sc[nt][0] = __expf(sc[nt][0] - mn0);
            sc[nt][1] = __expf(sc[nt][1] - mn0);
            sc[nt][2] = __expf(sc[nt][2] - mn1);
            sc[nt][3] = __expf(sc[nt][3] - mn1);
            lsum0 += sc[nt][0] + sc[nt][1];
            lsum1 += sc[nt][2] + sc[nt][3];
        }

        // P @ V : 4 key-slices (16) x 4 ch-tiles (8)
        #pragma unroll
        for (int ks = 0; ks < 4; ks++) {
            uint32_t a0 = pack_h2(sc[2*ks][0],   sc[2*ks][1]);
            uint32_t a1 = pack_h2(sc[2*ks][2],   sc[2*ks][3]);
            uint32_t a2 = pack_h2(sc[2*ks+1][0], sc[2*ks+1][1]);
            uint32_t a3 = pack_h2(sc[2*ks+1][2], sc[2*ks+1][3]);
            #pragma unroll
            for (int j = 0; j < 2; j++) {       // ch-tile pairs (16 ch)
                uint32_t b0, b1, b2, b3;
                uint32_t addr = sv + (uint32_t)(j*16 + (lane & 7) + ((lane >> 4) & 1)*8)*144
                              + (uint32_t)(ks*32 + ((lane >> 3) & 1)*16);
                ldmatrix_x4(b0, b1, b2, b3, addr);
                mma16816(O[2*j],   a0, a1, a2, a3, b0, b1);
                mma16816(O[2*j+1], a0, a1, a2, a3, b2, b3);
            }
        }
    }

    // Final normalization + store to g_a (fp32 channel-planar)
    lsum0 += __shfl_xor_sync(0xffffffffu, lsum0, 1);
    lsum0 += __shfl_xor_sync(0xffffffffu, lsum0, 2);
    lsum1 += __shfl_xor_sync(0xffffffffu, lsum1, 1);
    lsum1 += __shfl_xor_sync(0xffffffffu, lsum1, 2);
    float inv0 = 1.f / lsum0, inv1 = 1.f / lsum1;

    const int row0 = q0 + m0 + (lane >> 2);
    const int cp = (lane & 3)*2;
    float* abase = g_a + (size_t)(n*CC + g*CG)*HW;
    #pragma unroll
    for (int nt = 0; nt < 4; nt++) {
        int ch = nt*8 + cp;
        abase[(size_t)ch*HW + row0]           = O[nt][0]*inv0;
        abase[(size_t)(ch+1)*HW + row0]       = O[nt][1]*inv0;
        abase[(size_t)ch*HW + row0 + 8]       = O[nt][2]*inv1;
        abase[(size_t)(ch+1)*HW + row0 + 8]   = O[nt][3]*inv1;
    }
}

// ---------------------------------------------------------------------------
// Kernel 4: LSTM epilogue (unchanged)
// ---------------------------------------------------------------------------
__device__ __forceinline__ float sigmoidf_(float x) { return 1.f / (1.f + __expf(-x)); }

__global__ __launch_bounds__(256) void lstm_kernel(
    const float* __restrict__ Wa0, const float* __restrict__ Wa1,
    const float* __restrict__ Wa2, const float* __restrict__ Wa3,
    const float* __restrict__ b0,  const float* __restrict__ b1,
    const float* __restrict__ b2,  const float* __restrict__ b3,
    const float* __restrict__ c_prev, float* __restrict__ out)
{
    __shared__ float s_a[CC][8];
    const int n  = blockIdx.y;
    const int p0 = blockIdx.x * 8;
    const int t  = threadIdx.x;

    for (int i = t; i < CC*8; i += 256) {
        int ch = i >> 3, p = i & 7;
        s_a[ch][p] = g_a[((size_t)(n*CC + ch))*HW + p0 + p];
    }
    __syncthreads();

    const int c = t, g = c >> 5;
    float a0[8], a1[8], a2[8], a3[8];
    #pragma unroll
    for (int p = 0; p < 8; p++) { a0[p] = a1[p] = a2[p] = a3[p] = 0.f; }

    const float* wa0 = Wa0 + c*CG;
    const float* wa1 = Wa1 + c*CG;
    const float* wa2 = Wa2 + c*CG;
    const float* wa3 = Wa3 + c*CG;
    for (int cg = 0; cg < CG; cg++) {
        float w0 = wa0[cg], w1 = wa1[cg], w2 = wa2[cg], w3 = wa3[cg];
        const float* ar = s_a[g*CG + cg];
        #pragma unroll
        for (int p = 0; p < 8; p++) {
            float av = ar[p];
            a0[p] = fmaf(w0, av, a0[p]);
            a1[p] = fmaf(w1, av, a1[p]);
            a2[p] = fmaf(w2, av, a2[p]);
            a3[p] = fmaf(w3, av, a3[p]);
        }
    }

    const float bi = b0[c], bf = b1[c], bg = b2[c], bo = b3[c];
    const int idx0 = (n*CC + c)*HW + p0;
    #pragma unroll
    for (int p = 0; p < 8; p++) {
        int idx = idx0 + p;
        float gi = sigmoidf_(a0[p] + g_gate[                 idx] + bi);
        float gf = sigmoidf_(a1[p] + g_gate[  STRIDE_GATE  + idx] + bf);
        float gg = tanhf    (a2[p] + g_gate[2*STRIDE_GATE  + idx] + bg);
        float go = sigmoidf_(a3[p] + g_gate[3*STRIDE_GATE  + idx] + bo);
        float cn = gf * c_prev[idx] + gi * gg;
        out[idx] = go * tanhf(cn);
    }
}

// ---------------------------------------------------------------------------
extern "C" void kernel_launch(void* const* d_in, const int* in_sizes, int n_in,
                              void* d_out, int out_size)
{
    const float* inp    = (const float*)d_in[0];
    const float* h_prev = (const float*)d_in[1];
    const float* c_prev = (const float*)d_in[2];
    const float* Wx     = (const float*)d_in[3];
    const float* Wxg    = (const float*)d_in[4];
    const float* tau    = (const float*)d_in[5];
    const float* Wq     = (const float*)d_in[6];
    const float* Wk     = (const float*)d_in[7];
    const float* Wv     = (const float*)d_in[8];
    const float* Wa_i   = (const float*)d_in[9];
    const float* Wxh_i  = (const float*)d_in[10];
    const float* b_i    = (const float*)d_in[11];
    const float* Wa_f   = (const float*)d_in[12];
    const float* Wxh_f  = (const float*)d_in[13];
    const float* b_f    = (const float*)d_in[14];
    const float* Wa_g   = (const float*)d_in[15];
    const float* Wxh_g  = (const float*)d_in[16];
    const float* b_g    = (const float*)d_in[17];
    const float* Wa_o   = (const float*)d_in[18];
    const float* Wxh_o  = (const float*)d_in[19];
    const float* b_o    = (const float*)d_in[20];
    float* out = (float*)d_out;

    cudaFuncSetAttribute(conv_same_mma,
                         cudaFuncAttributeMaxDynamicSharedMemorySize, SMT_CONV);
    cudaFuncSetAttribute(conv_valid_mma,
                         cudaFuncAttributeMaxDynamicSharedMemorySize, SMT_CONV);

    prep_wfrag      <<<9072, 256>>>(Wq, Wxh_i, Wxh_f, Wxh_g, Wxh_o, Wk, Wv);
    proj_kernel     <<<dim3(HW/32, NB), 256>>>(inp, h_prev, Wx, Wxg);
    conv_same_mma   <<<dim3(18, 5, NB*GG), 128, SMT_CONV>>>(tau);
    conv_valid_mma  <<<dim3(15, 2, NB*GG), 128, SMT_CONV>>>();
    attn_mma        <<<dim3(36, NB*GG), 128>>>();
    lstm_kernel     <<<dim3(HW/8, NB), 256>>>(Wa_i, Wa_f, Wa_g, Wa_o,
                                              b_i, b_f, b_g, b_o, c_prev, out);
}

// round 7
// speedup vs baseline: 6.7922x; 1.1745x over previous
#include <cuda_runtime.h>
#include <cuda_fp16.h>
#include <math.h>
#include <stdint.h>

// Problem constants
#define NB   4
#define CI   64
#define CC   256
#define GG   8
#define CG   32
#define KK   9
#define HH   48
#define WW   48
#define HW   (HH*WW)   // 2304
#define HD   40
#define WD   40
#define DD   (HD*WD)   // 1600
#define C2   (2*CC)
#define CPG  64        // 2C/G
#define STRIDE_GATE (NB*CC*HW)

typedef unsigned long long u64;

// Scratch (static device globals; allocation-free rule)
__device__ __half   g_xh16[NB*GG*HW*CPG];              // fp16 [n][g][pos][ci]
__device__ uint32_t g_wfrag[7*GG*81*16*32*2];          // B frags [conv][g][tap][ks*4+ns][lane][2]
__device__ __half   g_q16 [NB*GG*HW*CG];               // q*tau  fp16 [n][g][pos][32]
__device__ __half   g_k16 [NB*GG*DD*CG];               // k      fp16 [n][g][key][32]
__device__ __half   g_v16 [NB*GG*CG*DD];               // v      fp16 [n][g][ch][key]
__device__ float    g_a   [NB*CC*HW];
__device__ float    g_gate[4*STRIDE_GATE];

// ---------------------------------------------------------------------------
// mma.sync helpers (compute_103-legal)
// ---------------------------------------------------------------------------
__device__ __forceinline__ uint32_t smem_u32(const void* p) {
    uint32_t a;
    asm("{ .reg .u64 t; cvta.to.shared.u64 t, %1; cvt.u32.u64 %0, t; }"
        : "=r"(a) : "l"(p));
    return a;
}

__device__ __forceinline__ void ldmatrix_x4(uint32_t& r0, uint32_t& r1,
                                            uint32_t& r2, uint32_t& r3,
                                            uint32_t addr) {
    asm volatile("ldmatrix.sync.aligned.m8n8.x4.shared.b16 {%0,%1,%2,%3}, [%4];"
                 : "=r"(r0), "=r"(r1), "=r"(r2), "=r"(r3) : "r"(addr));
}

__device__ __forceinline__ void mma16816(float* c, uint32_t a0, uint32_t a1,
                                         uint32_t a2, uint32_t a3,
                                         uint32_t b0, uint32_t b1) {
    asm volatile("mma.sync.aligned.m16n8k16.row.col.f32.f16.f16.f32 "
                 "{%0,%1,%2,%3}, {%4,%5,%6,%7}, {%8,%9}, {%0,%1,%2,%3};"
                 : "+f"(c[0]), "+f"(c[1]), "+f"(c[2]), "+f"(c[3])
                 : "r"(a0), "r"(a1), "r"(a2), "r"(a3), "r"(b0), "r"(b1));
}

__device__ __forceinline__ uint32_t pack_h2(float a, float b) {
    __half2 h = __floats2half2_rn(a, b);
    return *reinterpret_cast<uint32_t*>(&h);
}

// ---------------------------------------------------------------------------
// Weight prep: build m16n8k16 B-fragments (unchanged)
// ---------------------------------------------------------------------------
__global__ __launch_bounds__(256) void prep_wfrag(
    const float* __restrict__ Wq, const float* __restrict__ Wi,
    const float* __restrict__ Wf, const float* __restrict__ Wg2,
    const float* __restrict__ Wo, const float* __restrict__ Wk,
    const float* __restrict__ Wv)
{
    int idx = blockIdx.x * 256 + threadIdx.x;
    int conv = idx / 331776;
    int rem  = idx - conv * 331776;
    int g    = rem / 41472;  rem -= g * 41472;
    int t    = rem >> 9;     rem &= 511;
    int ks   = rem >> 7;
    int ns   = (rem >> 5) & 3;
    int lane = rem & 31;

    const float* W = (conv == 0) ? Wq : (conv == 1) ? Wi : (conv == 2) ? Wf :
                     (conv == 3) ? Wg2 : (conv == 4) ? Wo : (conv == 5) ? Wk : Wv;

    int oc  = ns*8 + (lane >> 2);
    int ci0 = ks*16 + (lane & 3)*2;
    const float* wb = W + (size_t)(g*32 + oc)*5184 + t;

    __half2 h0 = __floats2half2_rn(wb[(ci0    )*81], wb[(ci0 + 1)*81]);
    __half2 h1 = __floats2half2_rn(wb[(ci0 + 8)*81], wb[(ci0 + 9)*81]);

    uint32_t* outp = g_wfrag + (size_t)((((conv*8 + g)*81 + t)*16 + ks*4 + ns)*32 + lane)*2;
    outp[0] = *reinterpret_cast<uint32_t*>(&h0);
    outp[1] = *reinterpret_cast<uint32_t*>(&h1);
}

// ---------------------------------------------------------------------------
// Kernel 1: proj (unchanged)
// ---------------------------------------------------------------------------
__global__ __launch_bounds__(256) void proj_kernel(
    const float* __restrict__ inp, const float* __restrict__ h,
    const float* __restrict__ Wx,  const float* __restrict__ Wxg)
{
    __shared__ float s_in[CI][32];
    __shared__ float s_h [CC][32];
    const int n  = blockIdx.y;
    const int p0 = blockIdx.x * 32;
    const int t  = threadIdx.x;

    for (int i = t; i < CI*32; i += 256) {
        int ch = i >> 5, p = i & 31;
        s_in[ch][p] = inp[(n*CI + ch)*HW + p0 + p];
    }
    for (int i = t; i < CC*32; i += 256) {
        int ch = i >> 5, p = i & 31;
        s_h[ch][p] = h[(n*CC + ch)*HW + p0 + p];
    }
    __syncthreads();

    const int c = t, g = c >> 5, cg = c & 31;
    float acc[32];
    #pragma unroll
    for (int p = 0; p < 32; p++) acc[p] = 0.f;

    const float4* wx4 = reinterpret_cast<const float4*>(Wx + c*CI);
    for (int ci4 = 0; ci4 < CI/4; ci4++) {
        float4 w = wx4[ci4];
        int cb = ci4 * 4;
        #pragma unroll
        for (int p = 0; p < 32; p++)
            acc[p] += w.x*s_in[cb][p] + w.y*s_in[cb+1][p]
                    + w.z*s_in[cb+2][p] + w.w*s_in[cb+3][p];
    }
    const float4* wg4 = reinterpret_cast<const float4*>(Wxg + c*CC);
    for (int ci4 = 0; ci4 < CC/4; ci4++) {
        float4 w = wg4[ci4];
        int cb = ci4 * 4;
        #pragma unroll
        for (int p = 0; p < 32; p++)
            acc[p] += w.x*s_h[cb][p] + w.y*s_h[cb+1][p]
                    + w.z*s_h[cb+2][p] + w.w*s_h[cb+3][p];
    }
    __half* x16 = g_xh16 + ((size_t)(n*GG + g)*HW + p0)*CPG;
    #pragma unroll
    for (int p = 0; p < 32; p++) {
        x16[(size_t)p*CPG + cg]      = __float2half(acc[p]);
        x16[(size_t)p*CPG + 32 + cg] = __float2half(s_h[c][p]);
    }
}

// ---------------------------------------------------------------------------
// Implicit-GEMM grouped 9x9 conv via mma.sync.
// 256-thread CTA, 16x16 output tile, 24 m16-slabs (3/warp).
// B fragments double-buffered in smem, prefetched 1 tap ahead via registers;
// ONE __syncthreads per tap.
// ---------------------------------------------------------------------------
#define TS2      592
#define SMB_OFF  (TS2*144)            // 85248
#define SMT_CONV (SMB_OFF + 8192)     // 93440 bytes

template<int OUTH, int OUTW, int PAD, int MODE>
__device__ __forceinline__ void conv_mma_body(
    const __half* __restrict__ xin,
    const uint32_t* __restrict__ bfrag,
    void* __restrict__ outv,
    int y0, int x0, float scale)
{
    extern __shared__ char smem[];
    const uint32_t s_tile = smem_u32(smem);
    const int tid = threadIdx.x, wid = tid >> 5, lane = tid & 31;

    // Input tile: 24 rows x 24 cols (576 slots used; 592 allocated)
    for (int i = tid; i < 576*8; i += 256) {
        int pos = i >> 3, sub = i & 7;
        int rr = pos / 24, cc = pos - rr*24;
        int gy = y0 + rr - PAD, gx = x0 + cc - PAD;
        uint4 v = make_uint4(0u, 0u, 0u, 0u);
        if (gy >= 0 && gy < HH && gx >= 0 && gx < WW)
            v = *reinterpret_cast<const uint4*>(xin + ((size_t)(gy*WW + gx) << 6) + (sub << 3));
        *reinterpret_cast<uint4*>(smem + pos*144 + sub*16) = v;
    }
    // Stage B tap 0 into buffer 0 (4KB = 1 uint4/thread)
    *reinterpret_cast<uint4*>(smem + SMB_OFF + tid*16) =
        __ldg(reinterpret_cast<const uint4*>(bfrag) + tid);
    __syncthreads();

    float acc[3][4][4];
    #pragma unroll
    for (int ss = 0; ss < 3; ss++)
        #pragma unroll
        for (int nt = 0; nt < 4; nt++)
            #pragma unroll
            for (int r = 0; r < 4; r++) acc[ss][nt][r] = 0.f;

    const int lrow = (lane & 7) + ((lane >> 3) & 1)*8;
    const int lkb  = ((lane >> 4) & 1)*16;

    for (int t = 0; t < 81; t++) {
        const int cur = t & 1;
        uint4 pf;
        if (t < 80)
            pf = __ldg(reinterpret_cast<const uint4*>(bfrag + (t+1)*1024) + tid);

        const uint32_t bb = (uint32_t)(SMB_OFF + cur*4096);
        const int tap_off = (t/9)*24 + (t%9);
        #pragma unroll
        for (int ks = 0; ks < 4; ks++) {
            uint32_t b[4][2];
            #pragma unroll
            for (int nt = 0; nt < 4; nt++) {
                u64 v = *reinterpret_cast<const u64*>(
                    smem + bb + ((ks*4 + nt)*32 + lane)*8);
                b[nt][0] = (uint32_t)v;
                b[nt][1] = (uint32_t)(v >> 32);
            }
            #pragma unroll
            for (int ss = 0; ss < 3; ss++) {
                const int pbase = (ss*8 + wid)*16 + tap_off;
                uint32_t a0, a1, a2, a3;
                ldmatrix_x4(a0, a1, a2, a3,
                            s_tile + (uint32_t)(pbase + lrow)*144 + (uint32_t)(ks*32 + lkb));
                #pragma unroll
                for (int nt = 0; nt < 4; nt++)
                    mma16816(acc[ss][nt], a0, a1, a2, a3, b[nt][0], b[nt][1]);
            }
        }
        if (t < 80)
            *reinterpret_cast<uint4*>(smem + SMB_OFF + (1-cur)*4096 + tid*16) = pf;
        __syncthreads();
    }

    const int r  = lane >> 2;
    const int cp = (lane & 3)*2;
    #pragma unroll
    for (int ss = 0; ss < 3; ss++) {
        const int mbase = (ss*8 + wid)*16;
        #pragma unroll
        for (int half = 0; half < 2; half++) {
            int m = mbase + r + half*8;
            int j = m / 24, x = m - j*24;
            if (x < 16) {
                int ox = x0 + x, oy = y0 + j;
                if (ox < OUTW && oy < OUTH) {
                    int off = oy*OUTW + ox;
                    #pragma unroll
                    for (int nt = 0; nt < 4; nt++) {
                        int oc = nt*8 + cp;
                        float v0 = acc[ss][nt][half*2];
                        float v1 = acc[ss][nt][half*2+1];
                        if (MODE == 0) {
                            float* o = (float*)outv;
                            o[(size_t)oc*OUTH*OUTW + off]     = v0;
                            o[(size_t)(oc+1)*OUTH*OUTW + off] = v1;
                        } else if (MODE == 1 || MODE == 2) {
                            __half* o = (__half*)outv;
                            __half2 h = __floats2half2_rn(v0*scale, v1*scale);
                            *reinterpret_cast<__half2*>(o + (size_t)off*32 + oc) = h;
                        } else {
                            __half* o = (__half*)outv;
                            o[(size_t)oc*OUTH*OUTW + off]     = __float2half(v0);
                            o[(size_t)(oc+1)*OUTH*OUTW + off] = __float2half(v1);
                        }
                    }
                }
            }
        }
    }
}

// SAME convs: q + 4 gates. grid (9, 5, 32): x = tile (3 rows x 3 cols of 16)
__global__ __launch_bounds__(256) void conv_same_mma(const float* __restrict__ tau)
{
    const int n = blockIdx.z >> 3, g = blockIdx.z & 7;
    const int conv = blockIdx.y;
    const int ty = blockIdx.x / 3, tx = blockIdx.x - ty*3;
    const __half* xin = g_xh16 + (size_t)(n*GG + g)*HW*CPG;
    const uint32_t* bf = g_wfrag + (size_t)(conv*GG + g)*81*1024;
    if (conv == 0) {
        conv_mma_body<HH, WW, 4, 1>(xin, bf,
            g_q16 + (size_t)(n*GG + g)*HW*CG, ty*16, tx*16, tau[g]);
    } else {
        conv_mma_body<HH, WW, 4, 0>(xin, bf,
            g_gate + (size_t)(conv-1)*STRIDE_GATE + (size_t)(n*CC + g*CG)*HW,
            ty*16, tx*16, 1.f);
    }
}

// VALID convs: k, v. grid (9, 2, 32)
__global__ __launch_bounds__(256) void conv_valid_mma()
{
    const int n = blockIdx.z >> 3, g = blockIdx.z & 7;
    const int sel = blockIdx.y;
    const int ty = blockIdx.x / 3, tx = blockIdx.x - ty*3;
    const __half* xin = g_xh16 + (size_t)(n*GG + g)*HW*CPG;
    const uint32_t* bf = g_wfrag + (size_t)((5 + sel)*GG + g)*81*1024;
    if (sel == 0) {
        conv_mma_body<HD, WD, 0, 2>(xin, bf,
            g_k16 + (size_t)(n*GG + g)*DD*CG, ty*16, tx*16, 1.f);
    } else {
        conv_mma_body<HD, WD, 0, 3>(xin, bf,
            g_v16 + (size_t)(n*GG + g)*CG*DD, ty*16, tx*16, 1.f);
    }
}

// ---------------------------------------------------------------------------
// Kernel 3: flash-style mma attention (unchanged)
// ---------------------------------------------------------------------------
__global__ __launch_bounds__(128) void attn_mma()
{
    __shared__ __align__(16) char s_q[64*80];
    __shared__ __align__(16) char s_k[64*80];
    __shared__ __align__(16) char s_v[32*144];
    const int tid = threadIdx.x, wid = tid >> 5, lane = tid & 31;
    const int n = blockIdx.y >> 3, g = blockIdx.y & 7;
    const int q0 = blockIdx.x * 64;

    const __half* qsrc = g_q16 + (size_t)(n*GG + g)*HW*CG;
    const __half* ksrc = g_k16 + (size_t)(n*GG + g)*DD*CG;
    const __half* vsrc = g_v16 + (size_t)(n*GG + g)*CG*DD;

    for (int i = tid; i < 256; i += 128) {
        int row = i >> 2, sub = i & 3;
        *reinterpret_cast<uint4*>(s_q + row*80 + sub*16) =
            *reinterpret_cast<const uint4*>(
                reinterpret_cast<const char*>(qsrc + (size_t)(q0 + row)*32) + sub*16);
    }
    __syncthreads();

    const int m0 = wid*16;
    uint32_t aq[2][4];
    #pragma unroll
    for (int ks = 0; ks < 2; ks++) {
        uint32_t addr = smem_u32(s_q) + (uint32_t)(m0 + (lane & 15))*80
                      + (uint32_t)(ks*32 + (lane >> 4)*16);
        ldmatrix_x4(aq[ks][0], aq[ks][1], aq[ks][2], aq[ks][3], addr);
    }

    float O[4][4];
    #pragma unroll
    for (int nt = 0; nt < 4; nt++)
        #pragma unroll
        for (int r = 0; r < 4; r++) O[nt][r] = 0.f;
    float mrun0 = -1e30f, mrun1 = -1e30f, lsum0 = 0.f, lsum1 = 0.f;

    const uint32_t sk = smem_u32(s_k), sv = smem_u32(s_v);

    for (int chn = 0; chn < 25; chn++) {
        const int d0 = chn*64;
        __syncthreads();
        for (int i = tid; i < 256; i += 128) {
            int row = i >> 2, sub = i & 3;
            *reinterpret_cast<uint4*>(s_k + row*80 + sub*16) =
                *reinterpret_cast<const uint4*>(
                    reinterpret_cast<const char*>(ksrc + (size_t)(d0 + row)*32) + sub*16);
        }
        for (int i = tid; i < 256; i += 128) {
            int row = i >> 3, sub = i & 7;
            *reinterpret_cast<uint4*>(s_v + row*144 + sub*16) =
                *reinterpret_cast<const uint4*>(
                    reinterpret_cast<const char*>(vsrc + (size_t)row*DD + d0) + sub*16);
        }
        __syncthreads();

        float sc[8][4];
        #pragma unroll
        for (int nt = 0; nt < 8; nt++)
            #pragma unroll
            for (int r = 0; r < 4; r++) sc[nt][r] = 0.f;
        #pragma unroll
        for (int ks = 0; ks < 2; ks++) {
            #pragma unroll
            for (int j = 0; j < 4; j++) {
                uint32_t b0, b1, b2, b3;
                uint32_t addr = sk + (uint32_t)(j*16 + (lane & 7) + ((lane >> 4) & 1)*8)*80
                              + (uint32_t)(ks*32 + ((lane >> 3) & 1)*16);
                ldmatrix_x4(b0, b1, b2, b3, addr);
                mma16816(sc[2*j],   aq[ks][0], aq[ks][1], aq[ks][2], aq[ks][3], b0, b1);
                mma16816(sc[2*j+1], aq[ks][0], aq[ks][1], aq[ks][2], aq[ks][3], b2, b3);
            }
        }

        float ml0 = -1e30f, ml1 = -1e30f;
        #pragma unroll
        for (int nt = 0; nt < 8; nt++) {
            ml0 = fmaxf(ml0, fmaxf(sc[nt][0], sc[nt][1]));
            ml1 = fmaxf(ml1, fmaxf(sc[nt][2], sc[nt][3]));
        }
        ml0 = fmaxf(ml0, __shfl_xor_sync(0xffffffffu, ml0, 1));
        ml0 = fmaxf(ml0, __shfl_xor_sync(0xffffffffu, ml0, 2));
        ml1 = fmaxf(ml1, __shfl_xor_sync(0xffffffffu, ml1, 1));
        ml1 = fmaxf(ml1, __shfl_xor_sync(0xffffffffu, ml1, 2));
        float mn0 = fmaxf(mrun0, ml0), mn1 = fmaxf(mrun1, ml1);
        float scl0 = __expf(mrun0 - mn0), scl1 = __expf(mrun1 - mn1);
        mrun0 = mn0; mrun1 = mn1;
        lsum0 *= scl0; lsum1 *= scl1;
        #pragma unroll
        for (int nt = 0; nt < 4; nt++) {
            O[nt][0] *= scl0; O[nt][1] *= scl0;
            O[nt][2] *= scl1; O[nt][3] *= scl1;
        }
        #pragma unroll
        for (int nt = 0; nt < 8; nt++) {
            sc[nt][0] = __expf(sc[nt][0] - mn0);
            sc[nt][1] = __expf(sc[nt][1] - mn0);
            sc[nt][2] = __expf(sc[nt][2] - mn1);
            sc[nt][3] = __expf(sc[nt][3] - mn1);
            lsum0 += sc[nt][0] + sc[nt][1];
            lsum1 += sc[nt][2] + sc[nt][3];
        }

        #pragma unroll
        for (int ks = 0; ks < 4; ks++) {
            uint32_t a0 = pack_h2(sc[2*ks][0],   sc[2*ks][1]);
            uint32_t a1 = pack_h2(sc[2*ks][2],   sc[2*ks][3]);
            uint32_t a2 = pack_h2(sc[2*ks+1][0], sc[2*ks+1][1]);
            uint32_t a3 = pack_h2(sc[2*ks+1][2], sc[2*ks+1][3]);
            #pragma unroll
            for (int j = 0; j < 2; j++) {
                uint32_t b0, b1, b2, b3;
                uint32_t addr = sv + (uint32_t)(j*16 + (lane & 7) + ((lane >> 4) & 1)*8)*144
                              + (uint32_t)(ks*32 + ((lane >> 3) & 1)*16);
                ldmatrix_x4(b0, b1, b2, b3, addr);
                mma16816(O[2*j],   a0, a1, a2, a3, b0, b1);
                mma16816(O[2*j+1], a0, a1, a2, a3, b2, b3);
            }
        }
    }

    lsum0 += __shfl_xor_sync(0xffffffffu, lsum0, 1);
    lsum0 += __shfl_xor_sync(0xffffffffu, lsum0, 2);
    lsum1 += __shfl_xor_sync(0xffffffffu, lsum1, 1);
    lsum1 += __shfl_xor_sync(0xffffffffu, lsum1, 2);
    float inv0 = 1.f / lsum0, inv1 = 1.f / lsum1;

    const int row0 = q0 + m0 + (lane >> 2);
    const int cp = (lane & 3)*2;
    float* abase = g_a + (size_t)(n*CC + g*CG)*HW;
    #pragma unroll
    for (int nt = 0; nt < 4; nt++) {
        int ch = nt*8 + cp;
        abase[(size_t)ch*HW + row0]           = O[nt][0]*inv0;
        abase[(size_t)(ch+1)*HW + row0]       = O[nt][1]*inv0;
        abase[(size_t)ch*HW + row0 + 8]       = O[nt][2]*inv1;
        abase[(size_t)(ch+1)*HW + row0 + 8]   = O[nt][3]*inv1;
    }
}

// ---------------------------------------------------------------------------
// Kernel 4: LSTM epilogue (unchanged)
// ---------------------------------------------------------------------------
__device__ __forceinline__ float sigmoidf_(float x) { return 1.f / (1.f + __expf(-x)); }

__global__ __launch_bounds__(256) void lstm_kernel(
    const float* __restrict__ Wa0, const float* __restrict__ Wa1,
    const float* __restrict__ Wa2, const float* __restrict__ Wa3,
    const float* __restrict__ b0,  const float* __restrict__ b1,
    const float* __restrict__ b2,  const float* __restrict__ b3,
    const float* __restrict__ c_prev, float* __restrict__ out)
{
    __shared__ float s_a[CC][8];
    const int n  = blockIdx.y;
    const int p0 = blockIdx.x * 8;
    const int t  = threadIdx.x;

    for (int i = t; i < CC*8; i += 256) {
        int ch = i >> 3, p = i & 7;
        s_a[ch][p] = g_a[((size_t)(n*CC + ch))*HW + p0 + p];
    }
    __syncthreads();

    const int c = t, g = c >> 5;
    float a0[8], a1[8], a2[8], a3[8];
    #pragma unroll
    for (int p = 0; p < 8; p++) { a0[p] = a1[p] = a2[p] = a3[p] = 0.f; }

    const float* wa0 = Wa0 + c*CG;
    const float* wa1 = Wa1 + c*CG;
    const float* wa2 = Wa2 + c*CG;
    const float* wa3 = Wa3 + c*CG;
    for (int cg = 0; cg < CG; cg++) {
        float w0 = wa0[cg], w1 = wa1[cg], w2 = wa2[cg], w3 = wa3[cg];
        const float* ar = s_a[g*CG + cg];
        #pragma unroll
        for (int p = 0; p < 8; p++) {
            float av = ar[p];
            a0[p] = fmaf(w0, av, a0[p]);
            a1[p] = fmaf(w1, av, a1[p]);
            a2[p] = fmaf(w2, av, a2[p]);
            a3[p] = fmaf(w3, av, a3[p]);
        }
    }

    const float bi = b0[c], bf = b1[c], bg = b2[c], bo = b3[c];
    const int idx0 = (n*CC + c)*HW + p0;
    #pragma unroll
    for (int p = 0; p < 8; p++) {
        int idx = idx0 + p;
        float gi = sigmoidf_(a0[p] + g_gate[                 idx] + bi);
        float gf = sigmoidf_(a1[p] + g_gate[  STRIDE_GATE  + idx] + bf);
        float gg = tanhf    (a2[p] + g_gate[2*STRIDE_GATE  + idx] + bg);
        float go = sigmoidf_(a3[p] + g_gate[3*STRIDE_GATE  + idx] + bo);
        float cn = gf * c_prev[idx] + gi * gg;
        out[idx] = go * tanhf(cn);
    }
}

// ---------------------------------------------------------------------------
extern "C" void kernel_launch(void* const* d_in, const int* in_sizes, int n_in,
                              void* d_out, int out_size)
{
    const float* inp    = (const float*)d_in[0];
    const float* h_prev = (const float*)d_in[1];
    const float* c_prev = (const float*)d_in[2];
    const float* Wx     = (const float*)d_in[3];
    const float* Wxg    = (const float*)d_in[4];
    const float* tau    = (const float*)d_in[5];
    const float* Wq     = (const float*)d_in[6];
    const float* Wk     = (const float*)d_in[7];
    const float* Wv     = (const float*)d_in[8];
    const float* Wa_i   = (const float*)d_in[9];
    const float* Wxh_i  = (const float*)d_in[10];
    const float* b_i    = (const float*)d_in[11];
    const float* Wa_f   = (const float*)d_in[12];
    const float* Wxh_f  = (const float*)d_in[13];
    const float* b_f    = (const float*)d_in[14];
    const float* Wa_g   = (const float*)d_in[15];
    const float* Wxh_g  = (const float*)d_in[16];
    const float* b_g    = (const float*)d_in[17];
    const float* Wa_o   = (const float*)d_in[18];
    const float* Wxh_o  = (const float*)d_in[19];
    const float* b_o    = (const float*)d_in[20];
    float* out = (float*)d_out;

    cudaFuncSetAttribute(conv_same_mma,
                         cudaFuncAttributeMaxDynamicSharedMemorySize, SMT_CONV);
    cudaFuncSetAttribute(conv_valid_mma,
                         cudaFuncAttributeMaxDynamicSharedMemorySize, SMT_CONV);

    prep_wfrag      <<<9072, 256>>>(Wq, Wxh_i, Wxh_f, Wxh_g, Wxh_o, Wk, Wv);
    proj_kernel     <<<dim3(HW/32, NB), 256>>>(inp, h_prev, Wx, Wxg);
    conv_same_mma   <<<dim3(9, 5, NB*GG), 256, SMT_CONV>>>(tau);
    conv_valid_mma  <<<dim3(9, 2, NB*GG), 256, SMT_CONV>>>();
    attn_mma        <<<dim3(36, NB*GG), 128>>>();
    lstm_kernel     <<<dim3(HW/8, NB), 256>>>(Wa_i, Wa_f, Wa_g, Wa_o,
                                              b_i, b_f, b_g, b_o, c_prev, out);
}